// round 1
// baseline (speedup 1.0000x reference)
#include <cuda_runtime.h>
#include <cuda_bf16.h>
#include <cstddef>

// Problem constants
#define BATCH 2
#define SEQ   2048
#define EMB   1024
#define HEADS 16
#define DHEAD 64
#define ROWS  (BATCH*SEQ)          // 4096
#define FFDIM (4*EMB)              // 4096

// ---------------- scratch (allocation-free: __device__ globals) ----------------
__device__ float g_h   [ROWS*EMB];    // LN1 out, reused for LN2 out
__device__ float g_q   [ROWS*EMB];    // [B,S,H*DH]
__device__ float g_k   [ROWS*EMB];
__device__ float g_v   [ROWS*EMB];
__device__ float g_attn[ROWS*EMB];    // attention output [B,S,H*DH]
__device__ float g_x1  [ROWS*EMB];    // x + attn@Wproj + bproj
__device__ float g_ffn [ROWS*FFDIM];  // relu(h2@W1+b1)

// ---------------- LayerNorm: one block per row ----------------
__global__ void ln_kernel(const float* __restrict__ x,
                          const float* __restrict__ g,
                          const float* __restrict__ b,
                          float* __restrict__ out) {
    int row = blockIdx.x;
    const float* xr = x + (size_t)row * EMB;
    float v[4];
    float s = 0.f, ss = 0.f;
#pragma unroll
    for (int i = 0; i < 4; i++) {
        v[i] = xr[threadIdx.x + i * 256];
        s  += v[i];
        ss += v[i] * v[i];
    }
#pragma unroll
    for (int m = 16; m; m >>= 1) {
        s  += __shfl_xor_sync(0xffffffffu, s,  m);
        ss += __shfl_xor_sync(0xffffffffu, ss, m);
    }
    __shared__ float red[2][8];
    int warp = threadIdx.x >> 5, lane = threadIdx.x & 31;
    if (lane == 0) { red[0][warp] = s; red[1][warp] = ss; }
    __syncthreads();
    float S = 0.f, SS = 0.f;
#pragma unroll
    for (int w = 0; w < 8; w++) { S += red[0][w]; SS += red[1][w]; }
    float mean = S * (1.f / EMB);
    float var  = SS * (1.f / EMB) - mean * mean;
    float inv  = rsqrtf(var + 1e-5f);
    float* orow = out + (size_t)row * EMB;
#pragma unroll
    for (int i = 0; i < 4; i++) {
        int e = threadIdx.x + i * 256;
        orow[e] = (v[i] - mean) * inv * g[e] + b[e];
    }
}

// ---------------- Generic 128x128x8 SGEMM, 256 threads, 8x8 per thread -------
// HEADB: B element (k, n) lives at B[(n>>6)*K*64 + k*64 + (n&63)]  (Wq/Wk/Wv layout)
// Epilogue: C = [relu]( A*B + bias ) + residual   (flags; relu & residual never both set)
template<bool HEADB>
__global__ void __launch_bounds__(256, 2)
sgemm128(int M, int N, int K,
         const float* __restrict__ A, int lda,
         const float* __restrict__ B, int ldb,
         float* __restrict__ C, int ldc,
         const float* __restrict__ bias,
         const float* __restrict__ residual,
         int doRelu) {
    const int BM = 128, BN = 128, BK = 8;
    __shared__ float As[BK][BM];
    __shared__ float Bs[BK][BN];
    int t  = threadIdx.x;
    int m0 = blockIdx.y * BM;
    int n0 = blockIdx.x * BN;
    int arow = t >> 1, acol = (t & 1) * 4;     // A: one float4/thread
    int brow = t >> 5, bcol = (t & 31) * 4;    // B: one float4/thread
    int tx = t & 15, ty = t >> 4;

    float acc[8][8];
#pragma unroll
    for (int i = 0; i < 8; i++)
#pragma unroll
        for (int j = 0; j < 8; j++) acc[i][j] = 0.f;

    for (int k0 = 0; k0 < K; k0 += BK) {
        float4 av = *(const float4*)(A + (size_t)(m0 + arow) * lda + k0 + acol);
        As[acol + 0][arow] = av.x;
        As[acol + 1][arow] = av.y;
        As[acol + 2][arow] = av.z;
        As[acol + 3][arow] = av.w;
        float4 bv;
        if (HEADB) {
            int n = n0 + bcol;
            bv = *(const float4*)(B + (size_t)(n >> 6) * ((size_t)K * 64)
                                    + (size_t)(k0 + brow) * 64 + (n & 63));
        } else {
            bv = *(const float4*)(B + (size_t)(k0 + brow) * ldb + n0 + bcol);
        }
        *(float4*)&Bs[brow][bcol] = bv;
        __syncthreads();
#pragma unroll
        for (int kk = 0; kk < BK; kk++) {
            float ar[8], br[8];
            *(float4*)&ar[0] = *(const float4*)&As[kk][ty * 4];
            *(float4*)&ar[4] = *(const float4*)&As[kk][64 + ty * 4];
            *(float4*)&br[0] = *(const float4*)&Bs[kk][tx * 4];
            *(float4*)&br[4] = *(const float4*)&Bs[kk][64 + tx * 4];
#pragma unroll
            for (int i = 0; i < 8; i++)
#pragma unroll
                for (int j = 0; j < 8; j++)
                    acc[i][j] += ar[i] * br[j];
        }
        __syncthreads();
    }
#pragma unroll
    for (int i = 0; i < 8; i++) {
        int r = m0 + ((i < 4) ? (ty * 4 + i) : (64 + ty * 4 + i - 4));
#pragma unroll
        for (int j = 0; j < 8; j++) {
            int c = n0 + ((j < 4) ? (tx * 4 + j) : (64 + tx * 4 + j - 4));
            float v = acc[i][j];
            if (bias)     v += bias[c];
            if (doRelu)   v  = fmaxf(v, 0.f);
            if (residual) v += residual[(size_t)r * ldc + c];
            C[(size_t)r * ldc + c] = v;
        }
    }
}

// ---------------- Flash attention (no mask), fp32, 64x64 tiles -----------------
// Q,K,V,O layout: [B, S, H*DH]; per (b,h) slice is S x 64 with row stride 1024.
#define FPAD 68
__global__ void __launch_bounds__(256, 2)
flash_kernel(const float* __restrict__ Q, const float* __restrict__ K,
             const float* __restrict__ V, float* __restrict__ O) {
    extern __shared__ float sm[];
    float* Qs = sm;                    // [d][r]  d-major, pad 68
    float* Ks = Qs + 64 * FPAD;        // [d][c]
    float* Vs = Ks + 64 * FPAD;        // [c][d]
    float* Ps = Vs + 64 * FPAD;        // [r][c]
    int t  = threadIdx.x;
    int bh = blockIdx.y;
    int b  = bh >> 4, h = bh & 15;
    int row0 = blockIdx.x * 64;
    int tx = t & 15, ty = t >> 4;
    const float scale = 0.125f;  // DH^-0.5
    size_t base = (size_t)b * SEQ * EMB + (size_t)h * DHEAD;

    for (int i = t; i < 4096; i += 256) {
        int r = i >> 6, d = i & 63;
        Qs[d * FPAD + r] = Q[base + (size_t)(row0 + r) * EMB + d] * scale;
    }
    float m[4], l[4], acc[4][4];
#pragma unroll
    for (int i = 0; i < 4; i++) {
        m[i] = -1e30f; l[i] = 0.f;
#pragma unroll
        for (int j = 0; j < 4; j++) acc[i][j] = 0.f;
    }
    __syncthreads();

    for (int kt = 0; kt < SEQ; kt += 64) {
        for (int i = t; i < 4096; i += 256) {
            int c = i >> 6, d = i & 63;
            size_t ga = base + (size_t)(kt + c) * EMB + d;
            Ks[d * FPAD + c] = K[ga];
            Vs[c * FPAD + d] = V[ga];
        }
        __syncthreads();

        // S = Q K^T  (4x4 per thread)
        float s[4][4];
#pragma unroll
        for (int i = 0; i < 4; i++)
#pragma unroll
            for (int j = 0; j < 4; j++) s[i][j] = 0.f;
        for (int d = 0; d < 64; d++) {
            float4 q4 = *(const float4*)&Qs[d * FPAD + ty * 4];
            float4 k4 = *(const float4*)&Ks[d * FPAD + tx * 4];
            float qa[4] = {q4.x, q4.y, q4.z, q4.w};
            float ka[4] = {k4.x, k4.y, k4.z, k4.w};
#pragma unroll
            for (int i = 0; i < 4; i++)
#pragma unroll
                for (int j = 0; j < 4; j++)
                    s[i][j] += qa[i] * ka[j];
        }

        // online softmax update (row reduce across the 16 tx lanes)
#pragma unroll
        for (int i = 0; i < 4; i++) {
            float mx = s[i][0];
#pragma unroll
            for (int j = 1; j < 4; j++) mx = fmaxf(mx, s[i][j]);
#pragma unroll
            for (int msk = 1; msk < 16; msk <<= 1)
                mx = fmaxf(mx, __shfl_xor_sync(0xffffffffu, mx, msk));
            float mn   = fmaxf(m[i], mx);
            float corr = __expf(m[i] - mn);
            m[i] = mn;
            float rs = 0.f;
#pragma unroll
            for (int j = 0; j < 4; j++) {
                float p = __expf(s[i][j] - mn);
                s[i][j] = p;
                rs += p;
            }
#pragma unroll
            for (int msk = 1; msk < 16; msk <<= 1)
                rs += __shfl_xor_sync(0xffffffffu, rs, msk);
            l[i] = l[i] * corr + rs;
#pragma unroll
            for (int j = 0; j < 4; j++) acc[i][j] *= corr;
        }

        // stage P
#pragma unroll
        for (int i = 0; i < 4; i++)
            *(float4*)&Ps[(ty * 4 + i) * FPAD + tx * 4] =
                make_float4(s[i][0], s[i][1], s[i][2], s[i][3]);
        __syncthreads();

        // acc += P V
        for (int c = 0; c < 64; c++) {
            float4 v4 = *(const float4*)&Vs[c * FPAD + tx * 4];
            float va[4] = {v4.x, v4.y, v4.z, v4.w};
#pragma unroll
            for (int i = 0; i < 4; i++) {
                float p = Ps[(ty * 4 + i) * FPAD + c];
#pragma unroll
                for (int j = 0; j < 4; j++) acc[i][j] += p * va[j];
            }
        }
        __syncthreads();
    }

#pragma unroll
    for (int i = 0; i < 4; i++) {
        float inv = 1.f / l[i];
#pragma unroll
        for (int j = 0; j < 4; j++)
            O[base + (size_t)(row0 + ty * 4 + i) * EMB + tx * 4 + j] = acc[i][j] * inv;
    }
}

// ---------------- host orchestration ----------------
extern "C" void kernel_launch(void* const* d_in, const int* in_sizes, int n_in,
                              void* d_out, int out_size) {
    const float* x     = (const float*)d_in[0];
    const float* Wq    = (const float*)d_in[1];
    const float* Wk    = (const float*)d_in[2];
    const float* Wv    = (const float*)d_in[3];
    const float* Wproj = (const float*)d_in[4];
    const float* bproj = (const float*)d_in[5];
    const float* W1    = (const float*)d_in[6];
    const float* b1    = (const float*)d_in[7];
    const float* W2    = (const float*)d_in[8];
    const float* b2    = (const float*)d_in[9];
    const float* g1    = (const float*)d_in[10];
    const float* be1   = (const float*)d_in[11];
    const float* g2    = (const float*)d_in[12];
    const float* be2   = (const float*)d_in[13];
    float* out = (float*)d_out;

    void *ph, *pq, *pk, *pv, *pattn, *px1, *pffn;
    cudaGetSymbolAddress(&ph,    g_h);
    cudaGetSymbolAddress(&pq,    g_q);
    cudaGetSymbolAddress(&pk,    g_k);
    cudaGetSymbolAddress(&pv,    g_v);
    cudaGetSymbolAddress(&pattn, g_attn);
    cudaGetSymbolAddress(&px1,   g_x1);
    cudaGetSymbolAddress(&pffn,  g_ffn);
    float* f_h    = (float*)ph;
    float* f_q    = (float*)pq;
    float* f_k    = (float*)pk;
    float* f_v    = (float*)pv;
    float* f_attn = (float*)pattn;
    float* f_x1   = (float*)px1;
    float* f_ffn  = (float*)pffn;

    cudaFuncSetAttribute(flash_kernel,
                         cudaFuncAttributeMaxDynamicSharedMemorySize,
                         4 * 64 * FPAD * (int)sizeof(float));

    // LN1
    ln_kernel<<<ROWS, 256>>>(x, g1, be1, f_h);

    // QKV projections (head-batched B layout), M=4096, N=1024, K=1024
    dim3 gP(EMB / 128, ROWS / 128);  // (8, 32)
    sgemm128<true><<<gP, 256>>>(ROWS, EMB, EMB, f_h, EMB, Wq, 0, f_q, EMB,
                                nullptr, nullptr, 0);
    sgemm128<true><<<gP, 256>>>(ROWS, EMB, EMB, f_h, EMB, Wk, 0, f_k, EMB,
                                nullptr, nullptr, 0);
    sgemm128<true><<<gP, 256>>>(ROWS, EMB, EMB, f_h, EMB, Wv, 0, f_v, EMB,
                                nullptr, nullptr, 0);

    // attention (no mask)
    flash_kernel<<<dim3(SEQ / 64, BATCH * HEADS), 256,
                   4 * 64 * FPAD * (int)sizeof(float)>>>(f_q, f_k, f_v, f_attn);

    // x1 = x + attn @ Wproj + bproj
    sgemm128<false><<<gP, 256>>>(ROWS, EMB, EMB, f_attn, EMB, Wproj, EMB,
                                 f_x1, EMB, bproj, x, 0);

    // LN2 (reuse f_h)
    ln_kernel<<<ROWS, 256>>>(f_x1, g2, be2, f_h);

    // ffn hidden = relu(h2 @ W1 + b1), M=4096, N=4096, K=1024
    dim3 gF1(FFDIM / 128, ROWS / 128);  // (32, 32)
    sgemm128<false><<<gF1, 256>>>(ROWS, FFDIM, EMB, f_h, EMB, W1, FFDIM,
                                  f_ffn, FFDIM, b1, nullptr, 1);

    // out = x1 + hidden @ W2 + b2, M=4096, N=1024, K=4096
    sgemm128<false><<<gP, 256>>>(ROWS, EMB, FFDIM, f_ffn, FFDIM, W2, EMB,
                                 out, EMB, b2, f_x1, 0);
}

// round 4
// speedup vs baseline: 1.5824x; 1.5824x over previous
#include <cuda_runtime.h>
#include <cuda_bf16.h>
#include <cstdint>
#include <cstddef>

// Problem constants
#define BATCH 2
#define SEQ   2048
#define EMB   1024
#define HEADS 16
#define DHEAD 64
#define ROWS  (BATCH*SEQ)          // 4096
#define FFDIM (4*EMB)              // 4096

// ---------------- scratch (allocation-free: __device__ globals) ----------------
__device__ float g_h   [ROWS*EMB];
__device__ float g_q   [ROWS*EMB];
__device__ float g_k   [ROWS*EMB];
__device__ float g_v   [ROWS*EMB];
__device__ float g_attn[ROWS*EMB];
__device__ float g_x1  [ROWS*EMB];
__device__ float g_ffn [ROWS*FFDIM];
// transposed weights, [N, K] K-major
__device__ float g_wqt [EMB*EMB];
__device__ float g_wkt [EMB*EMB];
__device__ float g_wvt [EMB*EMB];
__device__ float g_wpt [EMB*EMB];
__device__ float g_w1t [EMB*FFDIM];
__device__ float g_w2t [FFDIM*EMB];

// ======================= mma.sync tf32 helpers (portable PTX) ================
__device__ __forceinline__ float to_tf32(float x) {
    uint32_t u;
    asm("cvt.rna.tf32.f32 %0, %1;" : "=r"(u) : "f"(x));
    return __uint_as_float(u);
}
__device__ __forceinline__ void mma1688(float* c,
                                        float a0, float a1, float a2, float a3,
                                        float b0, float b1) {
    asm volatile(
        "mma.sync.aligned.m16n8k8.row.col.f32.tf32.tf32.f32 "
        "{%0,%1,%2,%3}, {%4,%5,%6,%7}, {%8,%9}, {%0,%1,%2,%3};"
        : "+f"(c[0]), "+f"(c[1]), "+f"(c[2]), "+f"(c[3])
        : "r"(__float_as_uint(a0)), "r"(__float_as_uint(a1)),
          "r"(__float_as_uint(a2)), "r"(__float_as_uint(a3)),
          "r"(__float_as_uint(b0)), "r"(__float_as_uint(b1)));
}

// ======================= tensor-core tf32 GEMM ===============================
// C[M,N] = A[M,K] * Bt[N,K]^T ; epilogue: C = [relu](D + bias) + residual
// BM=BN=128, BK=16, 256 threads (8 warps = 2x4), 64x32 per warp.
// Smem layout: S[k&3][row][k>>2], j-stride 520 floats (bank-shift pad).
#define JSTRIDE 520

__global__ void __launch_bounds__(256, 1)
gemm_mma(const float* __restrict__ A, const float* __restrict__ Bt,
         float* __restrict__ C,
         const float* __restrict__ bias,
         const float* __restrict__ residual,
         int doRelu, int K, int N) {
    __shared__ float As[2][4 * JSTRIDE];
    __shared__ float Bs[2][4 * JSTRIDE];
    int t = threadIdx.x;
    int lane = t & 31, wid = t >> 5;
    int g = lane >> 2, tg = lane & 3;
    int warp_m = wid & 1, warp_n = wid >> 1;
    int m0 = blockIdx.y * 128, n0 = blockIdx.x * 128;

    const float* Ab = A  + (size_t)m0 * K;
    const float* Bb = Bt + (size_t)n0 * K;

    float acc[4][4][4];
#pragma unroll
    for (int i = 0; i < 4; i++)
#pragma unroll
        for (int j = 0; j < 4; j++)
#pragma unroll
            for (int r = 0; r < 4; r++) acc[i][j][r] = 0.f;

    // global-load offsets: float4 index f = t + 256*i -> row = f>>2, c4 = f&3
    int f0 = t, f1 = t + 256;
    int ar0 = f0 >> 2, ac0 = (f0 & 3) * 4;
    int ar1 = f1 >> 2, ac1 = (f1 & 3) * 4;

    float4 pa0, pa1, pb0, pb1;
#define LDG_TILE(k0)                                                   \
    do {                                                               \
        pa0 = *(const float4*)(Ab + (size_t)ar0 * K + (k0) + ac0);     \
        pa1 = *(const float4*)(Ab + (size_t)ar1 * K + (k0) + ac1);     \
        pb0 = *(const float4*)(Bb + (size_t)ar0 * K + (k0) + ac0);     \
        pb1 = *(const float4*)(Bb + (size_t)ar1 * K + (k0) + ac1);     \
    } while (0)
#define STS_TILE(buf)                                                  \
    do {                                                               \
        As[buf][0 * JSTRIDE + f0] = to_tf32(pa0.x);                    \
        As[buf][1 * JSTRIDE + f0] = to_tf32(pa0.y);                    \
        As[buf][2 * JSTRIDE + f0] = to_tf32(pa0.z);                    \
        As[buf][3 * JSTRIDE + f0] = to_tf32(pa0.w);                    \
        As[buf][0 * JSTRIDE + f1] = to_tf32(pa1.x);                    \
        As[buf][1 * JSTRIDE + f1] = to_tf32(pa1.y);                    \
        As[buf][2 * JSTRIDE + f1] = to_tf32(pa1.z);                    \
        As[buf][3 * JSTRIDE + f1] = to_tf32(pa1.w);                    \
        Bs[buf][0 * JSTRIDE + f0] = to_tf32(pb0.x);                    \
        Bs[buf][1 * JSTRIDE + f0] = to_tf32(pb0.y);                    \
        Bs[buf][2 * JSTRIDE + f0] = to_tf32(pb0.z);                    \
        Bs[buf][3 * JSTRIDE + f0] = to_tf32(pb0.w);                    \
        Bs[buf][0 * JSTRIDE + f1] = to_tf32(pb1.x);                    \
        Bs[buf][1 * JSTRIDE + f1] = to_tf32(pb1.y);                    \
        Bs[buf][2 * JSTRIDE + f1] = to_tf32(pb1.z);                    \
        Bs[buf][3 * JSTRIDE + f1] = to_tf32(pb1.w);                    \
    } while (0)

    LDG_TILE(0);
    STS_TILE(0);
    __syncthreads();

    int NKt = K >> 4;
    for (int it = 0; it < NKt; it++) {
        int buf = it & 1;
        if (it + 1 < NKt) LDG_TILE((it + 1) << 4);

        // fragment loads (one float4 covers both k-steps)
        float4 af[8], bf[4];
#pragma unroll
        for (int mf = 0; mf < 4; mf++)
#pragma unroll
            for (int rr = 0; rr < 2; rr++) {
                int row = warp_m * 64 + mf * 16 + rr * 8 + g;
                af[mf * 2 + rr] = *(const float4*)&As[buf][tg * JSTRIDE + row * 4];
            }
#pragma unroll
        for (int nf = 0; nf < 4; nf++) {
            int n = warp_n * 32 + nf * 8 + g;
            bf[nf] = *(const float4*)&Bs[buf][tg * JSTRIDE + n * 4];
        }
#pragma unroll
        for (int mf = 0; mf < 4; mf++)
#pragma unroll
            for (int nf = 0; nf < 4; nf++) {
                mma1688(acc[mf][nf],
                        af[mf * 2].x, af[mf * 2 + 1].x,
                        af[mf * 2].y, af[mf * 2 + 1].y,
                        bf[nf].x, bf[nf].y);
                mma1688(acc[mf][nf],
                        af[mf * 2].z, af[mf * 2 + 1].z,
                        af[mf * 2].w, af[mf * 2 + 1].w,
                        bf[nf].z, bf[nf].w);
            }

        if (it + 1 < NKt) STS_TILE((it + 1) & 1);
        __syncthreads();
    }

    // epilogue
#pragma unroll
    for (int mf = 0; mf < 4; mf++) {
#pragma unroll
        for (int nf = 0; nf < 4; nf++) {
            int row = m0 + warp_m * 64 + mf * 16 + g;
            int col = n0 + warp_n * 32 + nf * 8 + 2 * tg;
            float b0 = 0.f, b1 = 0.f;
            if (bias) { b0 = bias[col]; b1 = bias[col + 1]; }
#pragma unroll
            for (int rr = 0; rr < 2; rr++) {
                int r = row + rr * 8;
                float v0 = acc[mf][nf][rr * 2 + 0] + b0;
                float v1 = acc[mf][nf][rr * 2 + 1] + b1;
                if (doRelu) { v0 = fmaxf(v0, 0.f); v1 = fmaxf(v1, 0.f); }
                if (residual) {
                    float2 rv = *(const float2*)(residual + (size_t)r * N + col);
                    v0 += rv.x; v1 += rv.y;
                }
                *(float2*)(C + (size_t)r * N + col) = make_float2(v0, v1);
            }
        }
    }
}

// ======================= weight transpose ===================================
// out[N,K] (K-major) from in: headMode ? in[(n>>6)*K*64 + k*64 + (n&63)] : in[k*N+n]
__global__ void transpose_w(const float* __restrict__ in, float* __restrict__ out,
                            int K, int N, int headMode) {
    __shared__ float tile[32][33];
    int k0 = blockIdx.y * 32, n0 = blockIdx.x * 32;
    int tx = threadIdx.x, ty = threadIdx.y;
    for (int i = ty; i < 32; i += 8) {
        int k = k0 + i, n = n0 + tx;
        float v = headMode
            ? in[(size_t)(n >> 6) * K * 64 + (size_t)k * 64 + (n & 63)]
            : in[(size_t)k * N + n];
        tile[i][tx] = v;
    }
    __syncthreads();
    for (int i = ty; i < 32; i += 8) {
        out[(size_t)(n0 + i) * K + k0 + tx] = tile[tx][i];
    }
}

// ======================= LayerNorm ==========================================
__global__ void ln_kernel(const float* __restrict__ x,
                          const float* __restrict__ g,
                          const float* __restrict__ b,
                          float* __restrict__ out) {
    int row = blockIdx.x;
    const float* xr = x + (size_t)row * EMB;
    float v[4];
    float s = 0.f, ss = 0.f;
#pragma unroll
    for (int i = 0; i < 4; i++) {
        v[i] = xr[threadIdx.x + i * 256];
        s += v[i]; ss += v[i] * v[i];
    }
#pragma unroll
    for (int m = 16; m; m >>= 1) {
        s  += __shfl_xor_sync(0xffffffffu, s,  m);
        ss += __shfl_xor_sync(0xffffffffu, ss, m);
    }
    __shared__ float red[2][8];
    int warp = threadIdx.x >> 5, lane = threadIdx.x & 31;
    if (lane == 0) { red[0][warp] = s; red[1][warp] = ss; }
    __syncthreads();
    float S = 0.f, SS = 0.f;
#pragma unroll
    for (int w = 0; w < 8; w++) { S += red[0][w]; SS += red[1][w]; }
    float mean = S * (1.f / EMB);
    float var  = SS * (1.f / EMB) - mean * mean;
    float inv  = rsqrtf(var + 1e-5f);
    float* orow = out + (size_t)row * EMB;
#pragma unroll
    for (int i = 0; i < 4; i++) {
        int e = threadIdx.x + i * 256;
        orow[e] = (v[i] - mean) * inv * g[e] + b[e];
    }
}

// ======================= Flash attention (fp32, no mask) =====================
#define FPAD 68
__global__ void __launch_bounds__(256, 2)
flash_kernel(const float* __restrict__ Q, const float* __restrict__ K,
             const float* __restrict__ V, float* __restrict__ O) {
    extern __shared__ float sm[];
    float* Qs = sm;
    float* Ks = Qs + 64 * FPAD;
    float* Vs = Ks + 64 * FPAD;
    float* Ps = Vs + 64 * FPAD;
    int t = threadIdx.x;
    int bh = blockIdx.y;
    int b = bh >> 4, h = bh & 15;
    int row0 = blockIdx.x * 64;
    int tx = t & 15, ty = t >> 4;
    const float scale = 0.125f;
    size_t base = (size_t)b * SEQ * EMB + (size_t)h * DHEAD;

    for (int i = t; i < 4096; i += 256) {
        int r = i >> 6, d = i & 63;
        Qs[d * FPAD + r] = Q[base + (size_t)(row0 + r) * EMB + d] * scale;
    }
    float m[4], l[4], acc[4][4];
#pragma unroll
    for (int i = 0; i < 4; i++) {
        m[i] = -1e30f; l[i] = 0.f;
#pragma unroll
        for (int j = 0; j < 4; j++) acc[i][j] = 0.f;
    }
    __syncthreads();

    for (int kt = 0; kt < SEQ; kt += 64) {
        for (int i = t; i < 4096; i += 256) {
            int c = i >> 6, d = i & 63;
            size_t ga = base + (size_t)(kt + c) * EMB + d;
            Ks[d * FPAD + c] = K[ga];
            Vs[c * FPAD + d] = V[ga];
        }
        __syncthreads();

        float s[4][4];
#pragma unroll
        for (int i = 0; i < 4; i++)
#pragma unroll
            for (int j = 0; j < 4; j++) s[i][j] = 0.f;
        for (int d = 0; d < 64; d++) {
            float4 q4 = *(const float4*)&Qs[d * FPAD + ty * 4];
            float4 k4 = *(const float4*)&Ks[d * FPAD + tx * 4];
            float qa[4] = {q4.x, q4.y, q4.z, q4.w};
            float ka[4] = {k4.x, k4.y, k4.z, k4.w};
#pragma unroll
            for (int i = 0; i < 4; i++)
#pragma unroll
                for (int j = 0; j < 4; j++)
                    s[i][j] += qa[i] * ka[j];
        }

#pragma unroll
        for (int i = 0; i < 4; i++) {
            float mx = s[i][0];
#pragma unroll
            for (int j = 1; j < 4; j++) mx = fmaxf(mx, s[i][j]);
#pragma unroll
            for (int msk = 1; msk < 16; msk <<= 1)
                mx = fmaxf(mx, __shfl_xor_sync(0xffffffffu, mx, msk));
            float mn = fmaxf(m[i], mx);
            float corr = __expf(m[i] - mn);
            m[i] = mn;
            float rs = 0.f;
#pragma unroll
            for (int j = 0; j < 4; j++) {
                float p = __expf(s[i][j] - mn);
                s[i][j] = p;
                rs += p;
            }
#pragma unroll
            for (int msk = 1; msk < 16; msk <<= 1)
                rs += __shfl_xor_sync(0xffffffffu, rs, msk);
            l[i] = l[i] * corr + rs;
#pragma unroll
            for (int j = 0; j < 4; j++) acc[i][j] *= corr;
        }

#pragma unroll
        for (int i = 0; i < 4; i++)
            *(float4*)&Ps[(ty * 4 + i) * FPAD + tx * 4] =
                make_float4(s[i][0], s[i][1], s[i][2], s[i][3]);
        __syncthreads();

        for (int c = 0; c < 64; c++) {
            float4 v4 = *(const float4*)&Vs[c * FPAD + tx * 4];
            float va[4] = {v4.x, v4.y, v4.z, v4.w};
#pragma unroll
            for (int i = 0; i < 4; i++) {
                float p = Ps[(ty * 4 + i) * FPAD + c];
#pragma unroll
                for (int j = 0; j < 4; j++) acc[i][j] += p * va[j];
            }
        }
        __syncthreads();
    }

#pragma unroll
    for (int i = 0; i < 4; i++) {
        float inv = 1.f / l[i];
#pragma unroll
        for (int j = 0; j < 4; j++)
            O[base + (size_t)(row0 + ty * 4 + i) * EMB + tx * 4 + j] = acc[i][j] * inv;
    }
}

// ======================= host orchestration =================================
extern "C" void kernel_launch(void* const* d_in, const int* in_sizes, int n_in,
                              void* d_out, int out_size) {
    const float* x     = (const float*)d_in[0];
    const float* Wq    = (const float*)d_in[1];
    const float* Wk    = (const float*)d_in[2];
    const float* Wv    = (const float*)d_in[3];
    const float* Wproj = (const float*)d_in[4];
    const float* bproj = (const float*)d_in[5];
    const float* W1    = (const float*)d_in[6];
    const float* b1    = (const float*)d_in[7];
    const float* W2    = (const float*)d_in[8];
    const float* b2    = (const float*)d_in[9];
    const float* g1    = (const float*)d_in[10];
    const float* be1   = (const float*)d_in[11];
    const float* g2    = (const float*)d_in[12];
    const float* be2   = (const float*)d_in[13];
    float* out = (float*)d_out;

    void *ph, *pq, *pk, *pv, *pattn, *px1, *pffn;
    void *pwq, *pwk, *pwv, *pwp, *pw1, *pw2;
    cudaGetSymbolAddress(&ph,    g_h);
    cudaGetSymbolAddress(&pq,    g_q);
    cudaGetSymbolAddress(&pk,    g_k);
    cudaGetSymbolAddress(&pv,    g_v);
    cudaGetSymbolAddress(&pattn, g_attn);
    cudaGetSymbolAddress(&px1,   g_x1);
    cudaGetSymbolAddress(&pffn,  g_ffn);
    cudaGetSymbolAddress(&pwq,   g_wqt);
    cudaGetSymbolAddress(&pwk,   g_wkt);
    cudaGetSymbolAddress(&pwv,   g_wvt);
    cudaGetSymbolAddress(&pwp,   g_wpt);
    cudaGetSymbolAddress(&pw1,   g_w1t);
    cudaGetSymbolAddress(&pw2,   g_w2t);
    float* f_h    = (float*)ph;
    float* f_q    = (float*)pq;
    float* f_k    = (float*)pk;
    float* f_v    = (float*)pv;
    float* f_attn = (float*)pattn;
    float* f_x1   = (float*)px1;
    float* f_ffn  = (float*)pffn;

    cudaFuncSetAttribute(flash_kernel, cudaFuncAttributeMaxDynamicSharedMemorySize,
                         4 * 64 * FPAD * (int)sizeof(float));

    dim3 tb(32, 8);
    transpose_w<<<dim3(EMB / 32,  EMB / 32), tb>>>(Wq, (float*)pwq, EMB, EMB, 1);
    transpose_w<<<dim3(EMB / 32,  EMB / 32), tb>>>(Wk, (float*)pwk, EMB, EMB, 1);
    transpose_w<<<dim3(EMB / 32,  EMB / 32), tb>>>(Wv, (float*)pwv, EMB, EMB, 1);
    transpose_w<<<dim3(EMB / 32,  EMB / 32), tb>>>(Wproj, (float*)pwp, EMB, EMB, 0);
    transpose_w<<<dim3(FFDIM / 32, EMB / 32), tb>>>(W1, (float*)pw1, EMB, FFDIM, 0);
    transpose_w<<<dim3(EMB / 32, FFDIM / 32), tb>>>(W2, (float*)pw2, FFDIM, EMB, 0);

    // LN1
    ln_kernel<<<ROWS, 256>>>(x, g1, be1, f_h);

    // QKV projections: M=4096, N=1024, K=1024
    dim3 gP(EMB / 128, ROWS / 128);   // (8, 32)
    gemm_mma<<<gP, 256>>>(f_h, (float*)pwq, f_q, nullptr, nullptr, 0, EMB, EMB);
    gemm_mma<<<gP, 256>>>(f_h, (float*)pwk, f_k, nullptr, nullptr, 0, EMB, EMB);
    gemm_mma<<<gP, 256>>>(f_h, (float*)pwv, f_v, nullptr, nullptr, 0, EMB, EMB);

    // attention
    flash_kernel<<<dim3(SEQ / 64, BATCH * HEADS), 256,
                   4 * 64 * FPAD * (int)sizeof(float)>>>(f_q, f_k, f_v, f_attn);

    // x1 = x + attn @ Wproj + bproj
    gemm_mma<<<gP, 256>>>(f_attn, (float*)pwp, f_x1, bproj, x, 0, EMB, EMB);

    // LN2
    ln_kernel<<<ROWS, 256>>>(f_x1, g2, be2, f_h);

    // ffn hidden = relu(h2 @ W1 + b1): M=4096, N=4096, K=1024
    dim3 gF1(FFDIM / 128, ROWS / 128);  // (32, 32)
    gemm_mma<<<gF1, 256>>>(f_h, (float*)pw1, f_ffn, b1, nullptr, 1, EMB, FFDIM);

    // out = x1 + hidden @ W2 + b2: M=4096, N=1024, K=4096
    gemm_mma<<<gP, 256>>>(f_ffn, (float*)pw2, out, b2, f_x1, 0, FFDIM, EMB);
}

// round 5
// speedup vs baseline: 1.8210x; 1.1508x over previous
#include <cuda_runtime.h>
#include <cuda_bf16.h>
#include <cstdint>
#include <cstddef>

// Problem constants
#define BATCH 2
#define SEQ   2048
#define EMB   1024
#define HEADS 16
#define DHEAD 64
#define ROWS  (BATCH*SEQ)          // 4096
#define FFDIM (4*EMB)              // 4096

// ---------------- scratch (allocation-free: __device__ globals) ----------------
__device__ float g_h   [ROWS*EMB];
__device__ float g_q   [ROWS*EMB];
__device__ float g_k   [ROWS*EMB];
__device__ float g_v   [ROWS*EMB];
__device__ float g_vt  [32*DHEAD*SEQ];   // V transposed: [bh][d][s]
__device__ float g_attn[ROWS*EMB];
__device__ float g_x1  [ROWS*EMB];
__device__ float g_ffn [ROWS*FFDIM];
// transposed weights, [N, K] K-major
__device__ float g_wqt [EMB*EMB];
__device__ float g_wkt [EMB*EMB];
__device__ float g_wvt [EMB*EMB];
__device__ float g_wpt [EMB*EMB];
__device__ float g_w1t [EMB*FFDIM];
__device__ float g_w2t [FFDIM*EMB];

// ======================= mma.sync tf32 helpers (portable PTX) ================
__device__ __forceinline__ float to_tf32(float x) {
    uint32_t u;
    asm("cvt.rna.tf32.f32 %0, %1;" : "=r"(u) : "f"(x));
    return __uint_as_float(u);
}
__device__ __forceinline__ void mma1688(float* c,
                                        float a0, float a1, float a2, float a3,
                                        float b0, float b1) {
    asm volatile(
        "mma.sync.aligned.m16n8k8.row.col.f32.tf32.tf32.f32 "
        "{%0,%1,%2,%3}, {%4,%5,%6,%7}, {%8,%9}, {%0,%1,%2,%3};"
        : "+f"(c[0]), "+f"(c[1]), "+f"(c[2]), "+f"(c[3])
        : "r"(__float_as_uint(a0)), "r"(__float_as_uint(a1)),
          "r"(__float_as_uint(a2)), "r"(__float_as_uint(a3)),
          "r"(__float_as_uint(b0)), "r"(__float_as_uint(b1)));
}

// ======================= tensor-core tf32 GEMM (unchanged from R4) ===========
#define JSTRIDE 520

__global__ void __launch_bounds__(256, 1)
gemm_mma(const float* __restrict__ A, const float* __restrict__ Bt,
         float* __restrict__ C,
         const float* __restrict__ bias,
         const float* __restrict__ residual,
         int doRelu, int K, int N) {
    __shared__ float As[2][4 * JSTRIDE];
    __shared__ float Bs[2][4 * JSTRIDE];
    int t = threadIdx.x;
    int lane = t & 31, wid = t >> 5;
    int g = lane >> 2, tg = lane & 3;
    int warp_m = wid & 1, warp_n = wid >> 1;
    int m0 = blockIdx.y * 128, n0 = blockIdx.x * 128;

    const float* Ab = A  + (size_t)m0 * K;
    const float* Bb = Bt + (size_t)n0 * K;

    float acc[4][4][4];
#pragma unroll
    for (int i = 0; i < 4; i++)
#pragma unroll
        for (int j = 0; j < 4; j++)
#pragma unroll
            for (int r = 0; r < 4; r++) acc[i][j][r] = 0.f;

    int f0 = t, f1 = t + 256;
    int ar0 = f0 >> 2, ac0 = (f0 & 3) * 4;
    int ar1 = f1 >> 2, ac1 = (f1 & 3) * 4;

    float4 pa0, pa1, pb0, pb1;
#define LDG_TILE(k0)                                                   \
    do {                                                               \
        pa0 = *(const float4*)(Ab + (size_t)ar0 * K + (k0) + ac0);     \
        pa1 = *(const float4*)(Ab + (size_t)ar1 * K + (k0) + ac1);     \
        pb0 = *(const float4*)(Bb + (size_t)ar0 * K + (k0) + ac0);     \
        pb1 = *(const float4*)(Bb + (size_t)ar1 * K + (k0) + ac1);     \
    } while (0)
#define STS_TILE(buf)                                                  \
    do {                                                               \
        As[buf][0 * JSTRIDE + f0] = to_tf32(pa0.x);                    \
        As[buf][1 * JSTRIDE + f0] = to_tf32(pa0.y);                    \
        As[buf][2 * JSTRIDE + f0] = to_tf32(pa0.z);                    \
        As[buf][3 * JSTRIDE + f0] = to_tf32(pa0.w);                    \
        As[buf][0 * JSTRIDE + f1] = to_tf32(pa1.x);                    \
        As[buf][1 * JSTRIDE + f1] = to_tf32(pa1.y);                    \
        As[buf][2 * JSTRIDE + f1] = to_tf32(pa1.z);                    \
        As[buf][3 * JSTRIDE + f1] = to_tf32(pa1.w);                    \
        Bs[buf][0 * JSTRIDE + f0] = to_tf32(pb0.x);                    \
        Bs[buf][1 * JSTRIDE + f0] = to_tf32(pb0.y);                    \
        Bs[buf][2 * JSTRIDE + f0] = to_tf32(pb0.z);                    \
        Bs[buf][3 * JSTRIDE + f0] = to_tf32(pb0.w);                    \
        Bs[buf][0 * JSTRIDE + f1] = to_tf32(pb1.x);                    \
        Bs[buf][1 * JSTRIDE + f1] = to_tf32(pb1.y);                    \
        Bs[buf][2 * JSTRIDE + f1] = to_tf32(pb1.z);                    \
        Bs[buf][3 * JSTRIDE + f1] = to_tf32(pb1.w);                    \
    } while (0)

    LDG_TILE(0);
    STS_TILE(0);
    __syncthreads();

    int NKt = K >> 4;
    for (int it = 0; it < NKt; it++) {
        int buf = it & 1;
        if (it + 1 < NKt) LDG_TILE((it + 1) << 4);

        float4 af[8], bf[4];
#pragma unroll
        for (int mf = 0; mf < 4; mf++)
#pragma unroll
            for (int rr = 0; rr < 2; rr++) {
                int row = warp_m * 64 + mf * 16 + rr * 8 + g;
                af[mf * 2 + rr] = *(const float4*)&As[buf][tg * JSTRIDE + row * 4];
            }
#pragma unroll
        for (int nf = 0; nf < 4; nf++) {
            int n = warp_n * 32 + nf * 8 + g;
            bf[nf] = *(const float4*)&Bs[buf][tg * JSTRIDE + n * 4];
        }
#pragma unroll
        for (int mf = 0; mf < 4; mf++)
#pragma unroll
            for (int nf = 0; nf < 4; nf++) {
                mma1688(acc[mf][nf],
                        af[mf * 2].x, af[mf * 2 + 1].x,
                        af[mf * 2].y, af[mf * 2 + 1].y,
                        bf[nf].x, bf[nf].y);
                mma1688(acc[mf][nf],
                        af[mf * 2].z, af[mf * 2 + 1].z,
                        af[mf * 2].w, af[mf * 2 + 1].w,
                        bf[nf].z, bf[nf].w);
            }

        if (it + 1 < NKt) STS_TILE((it + 1) & 1);
        __syncthreads();
    }

#pragma unroll
    for (int mf = 0; mf < 4; mf++) {
#pragma unroll
        for (int nf = 0; nf < 4; nf++) {
            int row = m0 + warp_m * 64 + mf * 16 + g;
            int col = n0 + warp_n * 32 + nf * 8 + 2 * tg;
            float b0 = 0.f, b1 = 0.f;
            if (bias) { b0 = bias[col]; b1 = bias[col + 1]; }
#pragma unroll
            for (int rr = 0; rr < 2; rr++) {
                int r = row + rr * 8;
                float v0 = acc[mf][nf][rr * 2 + 0] + b0;
                float v1 = acc[mf][nf][rr * 2 + 1] + b1;
                if (doRelu) { v0 = fmaxf(v0, 0.f); v1 = fmaxf(v1, 0.f); }
                if (residual) {
                    float2 rv = *(const float2*)(residual + (size_t)r * N + col);
                    v0 += rv.x; v1 += rv.y;
                }
                *(float2*)(C + (size_t)r * N + col) = make_float2(v0, v1);
            }
        }
    }
}

// ======================= weight transpose ===================================
__global__ void transpose_w(const float* __restrict__ in, float* __restrict__ out,
                            int K, int N, int headMode) {
    __shared__ float tile[32][33];
    int k0 = blockIdx.y * 32, n0 = blockIdx.x * 32;
    int tx = threadIdx.x, ty = threadIdx.y;
    for (int i = ty; i < 32; i += 8) {
        int k = k0 + i, n = n0 + tx;
        float v = headMode
            ? in[(size_t)(n >> 6) * K * 64 + (size_t)k * 64 + (n & 63)]
            : in[(size_t)k * N + n];
        tile[i][tx] = v;
    }
    __syncthreads();
    for (int i = ty; i < 32; i += 8) {
        out[(size_t)(n0 + i) * K + k0 + tx] = tile[tx][i];
    }
}

// ======================= V transpose: [b,s,h*64+d] -> [bh][d][s] =============
__global__ void transpose_v(const float* __restrict__ v, float* __restrict__ vt) {
    __shared__ float tile[32][33];
    int bh = blockIdx.z;
    int s0 = blockIdx.x * 32, d0 = blockIdx.y * 32;
    int b = bh >> 4, h = bh & 15;
    int tx = threadIdx.x, ty = threadIdx.y;
    for (int i = ty; i < 32; i += 8)
        tile[i][tx] = v[(size_t)(b * SEQ + s0 + i) * EMB + h * 64 + d0 + tx];
    __syncthreads();
    for (int i = ty; i < 32; i += 8)
        vt[((size_t)bh * 64 + d0 + i) * SEQ + s0 + tx] = tile[tx][i];
}

// ======================= LayerNorm ==========================================
__global__ void ln_kernel(const float* __restrict__ x,
                          const float* __restrict__ g,
                          const float* __restrict__ b,
                          float* __restrict__ out) {
    int row = blockIdx.x;
    const float* xr = x + (size_t)row * EMB;
    float v[4];
    float s = 0.f, ss = 0.f;
#pragma unroll
    for (int i = 0; i < 4; i++) {
        v[i] = xr[threadIdx.x + i * 256];
        s += v[i]; ss += v[i] * v[i];
    }
#pragma unroll
    for (int m = 16; m; m >>= 1) {
        s  += __shfl_xor_sync(0xffffffffu, s,  m);
        ss += __shfl_xor_sync(0xffffffffu, ss, m);
    }
    __shared__ float red[2][8];
    int warp = threadIdx.x >> 5, lane = threadIdx.x & 31;
    if (lane == 0) { red[0][warp] = s; red[1][warp] = ss; }
    __syncthreads();
    float S = 0.f, SS = 0.f;
#pragma unroll
    for (int w = 0; w < 8; w++) { S += red[0][w]; SS += red[1][w]; }
    float mean = S * (1.f / EMB);
    float var  = SS * (1.f / EMB) - mean * mean;
    float inv  = rsqrtf(var + 1e-5f);
    float* orow = out + (size_t)row * EMB;
#pragma unroll
    for (int i = 0; i < 4; i++) {
        int e = threadIdx.x + i * 256;
        orow[e] = (v[i] - mean) * inv * g[e] + b[e];
    }
}

// ======================= Flash attention, tensor-core tf32 ===================
// Br=128 (8 warps x 16 rows), Bc=64, d=64. No mask.
// Permuted smem layouts (SLAB % 32 == 4 -> conflict-free LDS.128 frags):
//   Q/P : (k&3)*2052 + row*16 + (k>>2)   rows=128
//   K/Vt: (k&3)*1028 + row*16 + (k>>2)   rows=64
#define QSLAB 2052
#define KSLAB 1028
#define QIDX(r, k) (((k) & 3) * QSLAB + (r) * 16 + ((k) >> 2))
#define KIDX(n, k) (((k) & 3) * KSLAB + (n) * 16 + ((k) >> 2))
#define SM_KS 8208
#define SM_VS 12320
#define SM_PS 16432
#define FLASH_SMEM (24640 * 4)

__global__ void __launch_bounds__(256)
flash_mma(const float* __restrict__ Q, const float* __restrict__ Kg,
          const float* __restrict__ Vt, float* __restrict__ O) {
    extern __shared__ float sm[];
    float* Qs = sm;
    float* Ks = sm + SM_KS;
    float* Vs = sm + SM_VS;
    float* Ps = sm + SM_PS;
    int t = threadIdx.x, lane = t & 31, w = t >> 5;
    int g = lane >> 2, tg = lane & 3;
    int bh = blockIdx.y;                 // b*16 + h
    int row0 = blockIdx.x * 128;
    size_t baseQ = (size_t)(bh >> 4) * SEQ * EMB + (size_t)(bh & 15) * DHEAD;
    size_t baseV = (size_t)bh * DHEAD * SEQ;

    // load Q tile (scaled, tf32)
    for (int i = t; i < 2048; i += 256) {
        int r = i >> 4, kq = i & 15;
        float4 qv = *(const float4*)(Q + baseQ + (size_t)(row0 + r) * EMB + kq * 4);
        Qs[QIDX(r, 4 * kq + 0)] = to_tf32(qv.x * 0.125f);
        Qs[QIDX(r, 4 * kq + 1)] = to_tf32(qv.y * 0.125f);
        Qs[QIDX(r, 4 * kq + 2)] = to_tf32(qv.z * 0.125f);
        Qs[QIDX(r, 4 * kq + 3)] = to_tf32(qv.w * 0.125f);
    }
    __syncthreads();

    int rA = w * 16 + g, rB = rA + 8;
    float4 qf[4][2];
#pragma unroll
    for (int kq = 0; kq < 4; kq++) {
        qf[kq][0] = *(const float4*)&Qs[tg * QSLAB + rA * 16 + 4 * kq];
        qf[kq][1] = *(const float4*)&Qs[tg * QSLAB + rB * 16 + 4 * kq];
    }

    float m0 = -1e30f, m1 = -1e30f, l0 = 0.f, l1 = 0.f;
    float oacc[8][4];
#pragma unroll
    for (int i = 0; i < 8; i++)
#pragma unroll
        for (int j = 0; j < 4; j++) oacc[i][j] = 0.f;

    for (int kt = 0; kt < SEQ; kt += 64) {
        __syncthreads();   // prior PV done with Ks/Vs
        for (int i = t; i < 1024; i += 256) {
            int n = i >> 4, kq = i & 15;
            float4 kv = *(const float4*)(Kg + baseQ + (size_t)(kt + n) * EMB + kq * 4);
            Ks[KIDX(n, 4 * kq + 0)] = to_tf32(kv.x);
            Ks[KIDX(n, 4 * kq + 1)] = to_tf32(kv.y);
            Ks[KIDX(n, 4 * kq + 2)] = to_tf32(kv.z);
            Ks[KIDX(n, 4 * kq + 3)] = to_tf32(kv.w);
        }
        for (int i = t; i < 1024; i += 256) {
            int d = i >> 4, cq = i & 15;
            float4 vv = *(const float4*)(Vt + baseV + (size_t)d * SEQ + kt + cq * 4);
            Vs[KIDX(d, 4 * cq + 0)] = to_tf32(vv.x);
            Vs[KIDX(d, 4 * cq + 1)] = to_tf32(vv.y);
            Vs[KIDX(d, 4 * cq + 2)] = to_tf32(vv.z);
            Vs[KIDX(d, 4 * cq + 3)] = to_tf32(vv.w);
        }
        __syncthreads();

        // S = Q K^T : 16x64 per warp
        float sacc[8][4];
#pragma unroll
        for (int i = 0; i < 8; i++)
#pragma unroll
            for (int j = 0; j < 4; j++) sacc[i][j] = 0.f;
#pragma unroll
        for (int kq = 0; kq < 4; kq++) {
            float4 a0 = qf[kq][0], a1 = qf[kq][1];
#pragma unroll
            for (int nb = 0; nb < 8; nb++) {
                float4 bv = *(const float4*)&Ks[tg * KSLAB + (nb * 8 + g) * 16 + 4 * kq];
                mma1688(sacc[nb], a0.x, a1.x, a0.y, a1.y, bv.x, bv.y);
                mma1688(sacc[nb], a0.z, a1.z, a0.w, a1.w, bv.z, bv.w);
            }
        }

        // online softmax (rows rA via c0,c1 ; rB via c2,c3)
        float mxA = -1e30f, mxB = -1e30f;
#pragma unroll
        for (int nb = 0; nb < 8; nb++) {
            mxA = fmaxf(mxA, fmaxf(sacc[nb][0], sacc[nb][1]));
            mxB = fmaxf(mxB, fmaxf(sacc[nb][2], sacc[nb][3]));
        }
        mxA = fmaxf(mxA, __shfl_xor_sync(0xffffffffu, mxA, 1));
        mxA = fmaxf(mxA, __shfl_xor_sync(0xffffffffu, mxA, 2));
        mxB = fmaxf(mxB, __shfl_xor_sync(0xffffffffu, mxB, 1));
        mxB = fmaxf(mxB, __shfl_xor_sync(0xffffffffu, mxB, 2));
        float mnA = fmaxf(m0, mxA), mnB = fmaxf(m1, mxB);
        float cA = __expf(m0 - mnA), cB = __expf(m1 - mnB);
        m0 = mnA; m1 = mnB;
        float rsA = 0.f, rsB = 0.f;
#pragma unroll
        for (int nb = 0; nb < 8; nb++) {
            sacc[nb][0] = __expf(sacc[nb][0] - mnA);
            sacc[nb][1] = __expf(sacc[nb][1] - mnA);
            sacc[nb][2] = __expf(sacc[nb][2] - mnB);
            sacc[nb][3] = __expf(sacc[nb][3] - mnB);
            rsA += sacc[nb][0] + sacc[nb][1];
            rsB += sacc[nb][2] + sacc[nb][3];
        }
        rsA += __shfl_xor_sync(0xffffffffu, rsA, 1);
        rsA += __shfl_xor_sync(0xffffffffu, rsA, 2);
        rsB += __shfl_xor_sync(0xffffffffu, rsB, 1);
        rsB += __shfl_xor_sync(0xffffffffu, rsB, 2);
        l0 = l0 * cA + rsA;
        l1 = l1 * cB + rsB;
#pragma unroll
        for (int db = 0; db < 8; db++) {
            oacc[db][0] *= cA; oacc[db][1] *= cA;
            oacc[db][2] *= cB; oacc[db][3] *= cB;
        }

        // write P (warp-local rows)
#pragma unroll
        for (int nb = 0; nb < 8; nb++) {
            int c0 = nb * 8 + 2 * tg;
            Ps[QIDX(rA, c0)]     = to_tf32(sacc[nb][0]);
            Ps[QIDX(rA, c0 + 1)] = to_tf32(sacc[nb][1]);
            Ps[QIDX(rB, c0)]     = to_tf32(sacc[nb][2]);
            Ps[QIDX(rB, c0 + 1)] = to_tf32(sacc[nb][3]);
        }
        __syncwarp();

        // O += P V  (B = Vt[d][c])
#pragma unroll
        for (int kq = 0; kq < 4; kq++) {
            float4 a0 = *(const float4*)&Ps[tg * QSLAB + rA * 16 + 4 * kq];
            float4 a1 = *(const float4*)&Ps[tg * QSLAB + rB * 16 + 4 * kq];
#pragma unroll
            for (int db = 0; db < 8; db++) {
                float4 bv = *(const float4*)&Vs[tg * KSLAB + (db * 8 + g) * 16 + 4 * kq];
                mma1688(oacc[db], a0.x, a1.x, a0.y, a1.y, bv.x, bv.y);
                mma1688(oacc[db], a0.z, a1.z, a0.w, a1.w, bv.z, bv.w);
            }
        }
    }

    float iA = 1.f / l0, iB = 1.f / l1;
#pragma unroll
    for (int db = 0; db < 8; db++) {
        int c = db * 8 + 2 * tg;
        *(float2*)(O + baseQ + (size_t)(row0 + rA) * EMB + c) =
            make_float2(oacc[db][0] * iA, oacc[db][1] * iA);
        *(float2*)(O + baseQ + (size_t)(row0 + rB) * EMB + c) =
            make_float2(oacc[db][2] * iB, oacc[db][3] * iB);
    }
}

// ======================= host orchestration =================================
extern "C" void kernel_launch(void* const* d_in, const int* in_sizes, int n_in,
                              void* d_out, int out_size) {
    const float* x     = (const float*)d_in[0];
    const float* Wq    = (const float*)d_in[1];
    const float* Wk    = (const float*)d_in[2];
    const float* Wv    = (const float*)d_in[3];
    const float* Wproj = (const float*)d_in[4];
    const float* bproj = (const float*)d_in[5];
    const float* W1    = (const float*)d_in[6];
    const float* b1    = (const float*)d_in[7];
    const float* W2    = (const float*)d_in[8];
    const float* b2    = (const float*)d_in[9];
    const float* g1    = (const float*)d_in[10];
    const float* be1   = (const float*)d_in[11];
    const float* g2    = (const float*)d_in[12];
    const float* be2   = (const float*)d_in[13];
    float* out = (float*)d_out;

    void *ph, *pq, *pk, *pv, *pvt, *pattn, *px1, *pffn;
    void *pwq, *pwk, *pwv, *pwp, *pw1, *pw2;
    cudaGetSymbolAddress(&ph,    g_h);
    cudaGetSymbolAddress(&pq,    g_q);
    cudaGetSymbolAddress(&pk,    g_k);
    cudaGetSymbolAddress(&pv,    g_v);
    cudaGetSymbolAddress(&pvt,   g_vt);
    cudaGetSymbolAddress(&pattn, g_attn);
    cudaGetSymbolAddress(&px1,   g_x1);
    cudaGetSymbolAddress(&pffn,  g_ffn);
    cudaGetSymbolAddress(&pwq,   g_wqt);
    cudaGetSymbolAddress(&pwk,   g_wkt);
    cudaGetSymbolAddress(&pwv,   g_wvt);
    cudaGetSymbolAddress(&pwp,   g_wpt);
    cudaGetSymbolAddress(&pw1,   g_w1t);
    cudaGetSymbolAddress(&pw2,   g_w2t);
    float* f_h    = (float*)ph;
    float* f_q    = (float*)pq;
    float* f_k    = (float*)pk;
    float* f_v    = (float*)pv;
    float* f_vt   = (float*)pvt;
    float* f_attn = (float*)pattn;
    float* f_x1   = (float*)px1;
    float* f_ffn  = (float*)pffn;

    cudaFuncSetAttribute(flash_mma, cudaFuncAttributeMaxDynamicSharedMemorySize,
                         FLASH_SMEM);

    dim3 tb(32, 8);
    transpose_w<<<dim3(EMB / 32,  EMB / 32), tb>>>(Wq, (float*)pwq, EMB, EMB, 1);
    transpose_w<<<dim3(EMB / 32,  EMB / 32), tb>>>(Wk, (float*)pwk, EMB, EMB, 1);
    transpose_w<<<dim3(EMB / 32,  EMB / 32), tb>>>(Wv, (float*)pwv, EMB, EMB, 1);
    transpose_w<<<dim3(EMB / 32,  EMB / 32), tb>>>(Wproj, (float*)pwp, EMB, EMB, 0);
    transpose_w<<<dim3(FFDIM / 32, EMB / 32), tb>>>(W1, (float*)pw1, EMB, FFDIM, 0);
    transpose_w<<<dim3(EMB / 32, FFDIM / 32), tb>>>(W2, (float*)pw2, FFDIM, EMB, 0);

    // LN1
    ln_kernel<<<ROWS, 256>>>(x, g1, be1, f_h);

    // QKV projections: M=4096, N=1024, K=1024
    dim3 gP(EMB / 128, ROWS / 128);   // (8, 32)
    gemm_mma<<<gP, 256>>>(f_h, (float*)pwq, f_q, nullptr, nullptr, 0, EMB, EMB);
    gemm_mma<<<gP, 256>>>(f_h, (float*)pwk, f_k, nullptr, nullptr, 0, EMB, EMB);
    gemm_mma<<<gP, 256>>>(f_h, (float*)pwv, f_v, nullptr, nullptr, 0, EMB, EMB);

    // V transpose for flash PV operand
    transpose_v<<<dim3(SEQ / 32, DHEAD / 32, 32), tb>>>(f_v, f_vt);

    // attention (tensor-core)
    flash_mma<<<dim3(SEQ / 128, 32), 256, FLASH_SMEM>>>(f_q, f_k, f_vt, f_attn);

    // x1 = x + attn @ Wproj + bproj
    gemm_mma<<<gP, 256>>>(f_attn, (float*)pwp, f_x1, bproj, x, 0, EMB, EMB);

    // LN2
    ln_kernel<<<ROWS, 256>>>(f_x1, g2, be2, f_h);

    // ffn hidden = relu(h2 @ W1 + b1): M=4096, N=4096, K=1024
    dim3 gF1(FFDIM / 128, ROWS / 128);  // (32, 32)
    gemm_mma<<<gF1, 256>>>(f_h, (float*)pw1, f_ffn, b1, nullptr, 1, EMB, FFDIM);

    // out = x1 + hidden @ W2 + b2: M=4096, N=1024, K=4096
    gemm_mma<<<gP, 256>>>(f_ffn, (float*)pw2, out, b2, f_x1, 0, FFDIM, EMB);
}

// round 6
// speedup vs baseline: 2.7415x; 1.5054x over previous
#include <cuda_runtime.h>
#include <cuda_fp16.h>
#include <cstdint>
#include <cstddef>

// Problem constants
#define BATCH 2
#define SEQ   2048
#define EMB   1024
#define HEADS 16
#define DHEAD 64
#define ROWS  (BATCH*SEQ)          // 4096
#define FFDIM (4*EMB)              // 4096

// ---------------- scratch (allocation-free: __device__ globals) ----------------
__device__ float g_h   [ROWS*EMB];
__device__ float g_q   [ROWS*EMB];
__device__ float g_k   [ROWS*EMB];
__device__ float g_v   [ROWS*EMB];
__device__ float g_vt  [32*DHEAD*SEQ];   // V transposed: [bh][d][s]
__device__ float g_attn[ROWS*EMB];
__device__ float g_x1  [ROWS*EMB];
__device__ float g_ffn [ROWS*FFDIM];
// transposed weights, [N, K] K-major
__device__ float g_wqt [EMB*EMB];
__device__ float g_wkt [EMB*EMB];
__device__ float g_wvt [EMB*EMB];
__device__ float g_wpt [EMB*EMB];
__device__ float g_w1t [EMB*FFDIM];
__device__ float g_w2t [FFDIM*EMB];

// ======================= fp16 mma helpers (portable PTX) ====================
__device__ __forceinline__ uint32_t packh2(float lo, float hi) {
    __half2 h = __floats2half2_rn(lo, hi);   // .x = lo (low 16 bits)
    return *reinterpret_cast<uint32_t*>(&h);
}
__device__ __forceinline__ void mmaf16(float* c,
                                       uint32_t a0, uint32_t a1,
                                       uint32_t a2, uint32_t a3,
                                       uint32_t b0, uint32_t b1) {
    asm volatile(
        "mma.sync.aligned.m16n8k16.row.col.f32.f16.f16.f32 "
        "{%0,%1,%2,%3}, {%4,%5,%6,%7}, {%8,%9}, {%0,%1,%2,%3};"
        : "+f"(c[0]), "+f"(c[1]), "+f"(c[2]), "+f"(c[3])
        : "r"(a0), "r"(a1), "r"(a2), "r"(a3), "r"(b0), "r"(b1));
}

// ======================= tensor-core fp16 GEMM ===============================
// C[M,N] = A[M,K]*Bt[N,K]^T, fp16 inputs (cvt at STS), fp32 accum.
// BM=BN=128, BK=32 fp32-k = 16 half2 units/row. 256 thr, 8 warps (2x4), 64x32/warp.
// Smem unit layout: S[(u&3)*520 + row*4 + (u>>2)]  (520 % 32 == 8 -> conflict-free)
#define GSLAB 520

__global__ void __launch_bounds__(256, 1)
gemm_mma(const float* __restrict__ A, const float* __restrict__ Bt,
         float* __restrict__ C,
         const float* __restrict__ bias,
         const float* __restrict__ residual,
         int doRelu, int K, int N) {
    __shared__ uint32_t As[2][4 * GSLAB];
    __shared__ uint32_t Bs[2][4 * GSLAB];
    int t = threadIdx.x;
    int lane = t & 31, wid = t >> 5;
    int g = lane >> 2, tg = lane & 3;
    int warp_m = wid & 1, warp_n = wid >> 1;
    int m0 = blockIdx.y * 128, n0 = blockIdx.x * 128;

    const float* Ab = A  + (size_t)m0 * K;
    const float* Bb = Bt + (size_t)n0 * K;

    float acc[4][4][4];
#pragma unroll
    for (int i = 0; i < 4; i++)
#pragma unroll
        for (int j = 0; j < 4; j++)
#pragma unroll
            for (int r = 0; r < 4; r++) acc[i][j][r] = 0.f;

    int row_ld = t >> 1;          // 0..127
    int kb = (t & 1) * 16;        // fp32-k offset within BK=32
    int ub = (t & 1) * 8;         // unit offset

    float4 pa[4], pb[4];
#define LDG_TILE(k0)                                                          \
    do {                                                                      \
        _Pragma("unroll")                                                     \
        for (int j = 0; j < 4; j++) {                                         \
            pa[j] = *(const float4*)(Ab + (size_t)row_ld * K + (k0) + kb + 4 * j); \
            pb[j] = *(const float4*)(Bb + (size_t)row_ld * K + (k0) + kb + 4 * j); \
        }                                                                     \
    } while (0)
#define STS_TILE(buf)                                                         \
    do {                                                                      \
        _Pragma("unroll")                                                     \
        for (int j = 0; j < 4; j++) {                                         \
            int u = ub + 2 * j;                                               \
            As[buf][(u & 3) * GSLAB + row_ld * 4 + (u >> 2)]                  \
                = packh2(pa[j].x, pa[j].y);                                   \
            As[buf][((u + 1) & 3) * GSLAB + row_ld * 4 + ((u + 1) >> 2)]      \
                = packh2(pa[j].z, pa[j].w);                                   \
            Bs[buf][(u & 3) * GSLAB + row_ld * 4 + (u >> 2)]                  \
                = packh2(pb[j].x, pb[j].y);                                   \
            Bs[buf][((u + 1) & 3) * GSLAB + row_ld * 4 + ((u + 1) >> 2)]      \
                = packh2(pb[j].z, pb[j].w);                                   \
        }                                                                     \
    } while (0)

    LDG_TILE(0);
    STS_TILE(0);
    __syncthreads();

    int NKt = K >> 5;
    for (int it = 0; it < NKt; it++) {
        int buf = it & 1;
        if (it + 1 < NKt) LDG_TILE((it + 1) << 5);

        uint4 a0f[4], a8f[4], bff[4];
#pragma unroll
        for (int mf = 0; mf < 4; mf++) {
            int row = warp_m * 64 + mf * 16 + g;
            a0f[mf] = *(const uint4*)&As[buf][tg * GSLAB + row * 4];
            a8f[mf] = *(const uint4*)&As[buf][tg * GSLAB + (row + 8) * 4];
        }
#pragma unroll
        for (int nf = 0; nf < 4; nf++) {
            int n = warp_n * 32 + nf * 8 + g;
            bff[nf] = *(const uint4*)&Bs[buf][tg * GSLAB + n * 4];
        }
#pragma unroll
        for (int mf = 0; mf < 4; mf++)
#pragma unroll
            for (int nf = 0; nf < 4; nf++) {
                mmaf16(acc[mf][nf], a0f[mf].x, a8f[mf].x, a0f[mf].y, a8f[mf].y,
                       bff[nf].x, bff[nf].y);
                mmaf16(acc[mf][nf], a0f[mf].z, a8f[mf].z, a0f[mf].w, a8f[mf].w,
                       bff[nf].z, bff[nf].w);
            }

        if (it + 1 < NKt) STS_TILE((it + 1) & 1);
        __syncthreads();
    }

    // epilogue (same C-fragment layout as m16n8k8)
#pragma unroll
    for (int mf = 0; mf < 4; mf++) {
#pragma unroll
        for (int nf = 0; nf < 4; nf++) {
            int row = m0 + warp_m * 64 + mf * 16 + g;
            int col = n0 + warp_n * 32 + nf * 8 + 2 * tg;
            float b0 = 0.f, b1 = 0.f;
            if (bias) { b0 = bias[col]; b1 = bias[col + 1]; }
#pragma unroll
            for (int rr = 0; rr < 2; rr++) {
                int r = row + rr * 8;
                float v0 = acc[mf][nf][rr * 2 + 0] + b0;
                float v1 = acc[mf][nf][rr * 2 + 1] + b1;
                if (doRelu) { v0 = fmaxf(v0, 0.f); v1 = fmaxf(v1, 0.f); }
                if (residual) {
                    float2 rv = *(const float2*)(residual + (size_t)r * N + col);
                    v0 += rv.x; v1 += rv.y;
                }
                *(float2*)(C + (size_t)r * N + col) = make_float2(v0, v1);
            }
        }
    }
}

// ======================= weight transpose ===================================
__global__ void transpose_w(const float* __restrict__ in, float* __restrict__ out,
                            int K, int N, int headMode) {
    __shared__ float tile[32][33];
    int k0 = blockIdx.y * 32, n0 = blockIdx.x * 32;
    int tx = threadIdx.x, ty = threadIdx.y;
    for (int i = ty; i < 32; i += 8) {
        int k = k0 + i, n = n0 + tx;
        float v = headMode
            ? in[(size_t)(n >> 6) * K * 64 + (size_t)k * 64 + (n & 63)]
            : in[(size_t)k * N + n];
        tile[i][tx] = v;
    }
    __syncthreads();
    for (int i = ty; i < 32; i += 8) {
        out[(size_t)(n0 + i) * K + k0 + tx] = tile[tx][i];
    }
}

// ======================= V transpose: [b,s,h*64+d] -> [bh][d][s] =============
__global__ void transpose_v(const float* __restrict__ v, float* __restrict__ vt) {
    __shared__ float tile[32][33];
    int bh = blockIdx.z;
    int s0 = blockIdx.x * 32, d0 = blockIdx.y * 32;
    int b = bh >> 4, h = bh & 15;
    int tx = threadIdx.x, ty = threadIdx.y;
    for (int i = ty; i < 32; i += 8)
        tile[i][tx] = v[(size_t)(b * SEQ + s0 + i) * EMB + h * 64 + d0 + tx];
    __syncthreads();
    for (int i = ty; i < 32; i += 8)
        vt[((size_t)bh * 64 + d0 + i) * SEQ + s0 + tx] = tile[tx][i];
}

// ======================= LayerNorm ==========================================
__global__ void ln_kernel(const float* __restrict__ x,
                          const float* __restrict__ g,
                          const float* __restrict__ b,
                          float* __restrict__ out) {
    int row = blockIdx.x;
    const float* xr = x + (size_t)row * EMB;
    float v[4];
    float s = 0.f, ss = 0.f;
#pragma unroll
    for (int i = 0; i < 4; i++) {
        v[i] = xr[threadIdx.x + i * 256];
        s += v[i]; ss += v[i] * v[i];
    }
#pragma unroll
    for (int m = 16; m; m >>= 1) {
        s  += __shfl_xor_sync(0xffffffffu, s,  m);
        ss += __shfl_xor_sync(0xffffffffu, ss, m);
    }
    __shared__ float red[2][8];
    int warp = threadIdx.x >> 5, lane = threadIdx.x & 31;
    if (lane == 0) { red[0][warp] = s; red[1][warp] = ss; }
    __syncthreads();
    float S = 0.f, SS = 0.f;
#pragma unroll
    for (int w = 0; w < 8; w++) { S += red[0][w]; SS += red[1][w]; }
    float mean = S * (1.f / EMB);
    float var  = SS * (1.f / EMB) - mean * mean;
    float inv  = rsqrtf(var + 1e-5f);
    float* orow = out + (size_t)row * EMB;
#pragma unroll
    for (int i = 0; i < 4; i++) {
        int e = threadIdx.x + i * 256;
        orow[e] = (v[i] - mean) * inv * g[e] + b[e];
    }
}

// ======================= Flash attention, fp16 tensor cores ==================
// Br=128 (8 warps x 16 rows), Bc=64, d=64. P stays in registers (FA2 style).
// Smem unit layout per sub-tile (16 units = 32 fp32-k):
//   Q (128 rows): sub*2080 + (uu&3)*520 + r*4 + (uu>>2)
//   K/V (64 rows): sub*1056 + (uu&3)*264 + r*4 + (uu>>2)
#define FQSLAB 520
#define FKSLAB 264
#define FQSUB  2080
#define FKSUB  1056

__global__ void __launch_bounds__(256)
flash_mma(const float* __restrict__ Q, const float* __restrict__ Kg,
          const float* __restrict__ Vt, float* __restrict__ O) {
    __shared__ uint32_t Qs[2 * FQSUB];
    __shared__ uint32_t Ks[2 * FKSUB];
    __shared__ uint32_t Vs[2 * FKSUB];
    int t = threadIdx.x, lane = t & 31, w = t >> 5;
    int g = lane >> 2, tg = lane & 3;
    int bh = blockIdx.y;
    int row0 = blockIdx.x * 128;
    size_t baseQ = (size_t)(bh >> 4) * SEQ * EMB + (size_t)(bh & 15) * DHEAD;
    size_t baseV = (size_t)bh * DHEAD * SEQ;

    // load Q tile (scaled, fp16)
    for (int i = t; i < 512; i += 256) {
        int r = i >> 2, q = i & 3;
        const float* src = Q + baseQ + (size_t)(row0 + r) * EMB + q * 16;
#pragma unroll
        for (int j = 0; j < 4; j++) {
            float4 p = *(const float4*)(src + 4 * j);
            int u = q * 8 + 2 * j;
            int s0 = u >> 4, uu0 = u & 15;
            Qs[s0 * FQSUB + (uu0 & 3) * FQSLAB + r * 4 + (uu0 >> 2)]
                = packh2(p.x * 0.125f, p.y * 0.125f);
            int u1 = u + 1, s1 = u1 >> 4, uu1 = u1 & 15;
            Qs[s1 * FQSUB + (uu1 & 3) * FQSLAB + r * 4 + (uu1 >> 2)]
                = packh2(p.z * 0.125f, p.w * 0.125f);
        }
    }
    __syncthreads();

    int rA = w * 16 + g, rB = rA + 8;
    uint4 qfA[2], qfB[2];
#pragma unroll
    for (int sub = 0; sub < 2; sub++) {
        qfA[sub] = *(const uint4*)&Qs[sub * FQSUB + tg * FQSLAB + rA * 4];
        qfB[sub] = *(const uint4*)&Qs[sub * FQSUB + tg * FQSLAB + rB * 4];
    }

    float m0 = -1e30f, m1 = -1e30f, l0 = 0.f, l1 = 0.f;
    float oacc[8][4];
#pragma unroll
    for (int i = 0; i < 8; i++)
#pragma unroll
        for (int j = 0; j < 4; j++) oacc[i][j] = 0.f;

    for (int kt = 0; kt < SEQ; kt += 64) {
        __syncthreads();   // prior iteration done reading Ks/Vs
        {
            int r = t >> 2, q = t & 3;
            const float* ksrc = Kg + baseQ + (size_t)(kt + r) * EMB + q * 16;
            const float* vsrc = Vt + baseV + (size_t)r * SEQ + kt + q * 16;
#pragma unroll
            for (int j = 0; j < 4; j++) {
                float4 pk = *(const float4*)(ksrc + 4 * j);
                float4 pv = *(const float4*)(vsrc + 4 * j);
                int u = q * 8 + 2 * j;
                int s0 = u >> 4, uu0 = u & 15;
                int o0 = s0 * FKSUB + (uu0 & 3) * FKSLAB + r * 4 + (uu0 >> 2);
                Ks[o0] = packh2(pk.x, pk.y);
                Vs[o0] = packh2(pv.x, pv.y);
                int u1 = u + 1, s1 = u1 >> 4, uu1 = u1 & 15;
                int o1 = s1 * FKSUB + (uu1 & 3) * FKSLAB + r * 4 + (uu1 >> 2);
                Ks[o1] = packh2(pk.z, pk.w);
                Vs[o1] = packh2(pv.z, pv.w);
            }
        }
        __syncthreads();

        // S = Q K^T : 16x64 per warp
        float sacc[8][4];
#pragma unroll
        for (int i = 0; i < 8; i++)
#pragma unroll
            for (int j = 0; j < 4; j++) sacc[i][j] = 0.f;
#pragma unroll
        for (int sub = 0; sub < 2; sub++) {
            uint4 qa = qfA[sub], qb = qfB[sub];
#pragma unroll
            for (int nb = 0; nb < 8; nb++) {
                uint4 kf = *(const uint4*)&Ks[sub * FKSUB + tg * FKSLAB
                                              + (nb * 8 + g) * 4];
                mmaf16(sacc[nb], qa.x, qb.x, qa.y, qb.y, kf.x, kf.y);
                mmaf16(sacc[nb], qa.z, qb.z, qa.w, qb.w, kf.z, kf.w);
            }
        }

        // online softmax (rows rA via c0,c1 ; rB via c2,c3)
        float mxA = -1e30f, mxB = -1e30f;
#pragma unroll
        for (int nb = 0; nb < 8; nb++) {
            mxA = fmaxf(mxA, fmaxf(sacc[nb][0], sacc[nb][1]));
            mxB = fmaxf(mxB, fmaxf(sacc[nb][2], sacc[nb][3]));
        }
        mxA = fmaxf(mxA, __shfl_xor_sync(0xffffffffu, mxA, 1));
        mxA = fmaxf(mxA, __shfl_xor_sync(0xffffffffu, mxA, 2));
        mxB = fmaxf(mxB, __shfl_xor_sync(0xffffffffu, mxB, 1));
        mxB = fmaxf(mxB, __shfl_xor_sync(0xffffffffu, mxB, 2));
        float mnA = fmaxf(m0, mxA), mnB = fmaxf(m1, mxB);
        float cA = __expf(m0 - mnA), cB = __expf(m1 - mnB);
        m0 = mnA; m1 = mnB;
        float rsA = 0.f, rsB = 0.f;
#pragma unroll
        for (int nb = 0; nb < 8; nb++) {
            sacc[nb][0] = __expf(sacc[nb][0] - mnA);
            sacc[nb][1] = __expf(sacc[nb][1] - mnA);
            sacc[nb][2] = __expf(sacc[nb][2] - mnB);
            sacc[nb][3] = __expf(sacc[nb][3] - mnB);
            rsA += sacc[nb][0] + sacc[nb][1];
            rsB += sacc[nb][2] + sacc[nb][3];
        }
        rsA += __shfl_xor_sync(0xffffffffu, rsA, 1);
        rsA += __shfl_xor_sync(0xffffffffu, rsA, 2);
        rsB += __shfl_xor_sync(0xffffffffu, rsB, 1);
        rsB += __shfl_xor_sync(0xffffffffu, rsB, 2);
        l0 = l0 * cA + rsA;
        l1 = l1 * cB + rsB;
#pragma unroll
        for (int db = 0; db < 8; db++) {
            oacc[db][0] *= cA; oacc[db][1] *= cA;
            oacc[db][2] *= cB; oacc[db][3] *= cB;
        }

        // pack P into registers (fragment-exact; no smem round trip)
        uint32_t a0[4], a1[4], a2[4], a3[4];
#pragma unroll
        for (int s = 0; s < 4; s++) {
            a0[s] = packh2(sacc[2 * s][0],     sacc[2 * s][1]);      // row rA
            a1[s] = packh2(sacc[2 * s][2],     sacc[2 * s][3]);      // row rB
            a2[s] = packh2(sacc[2 * s + 1][0], sacc[2 * s + 1][1]);  // rA, k+8
            a3[s] = packh2(sacc[2 * s + 1][2], sacc[2 * s + 1][3]);  // rB, k+8
        }

        // O += P V  (B = Vt[d][c] in Vs)
#pragma unroll
        for (int db = 0; db < 8; db++)
#pragma unroll
            for (int sub = 0; sub < 2; sub++) {
                uint4 vf = *(const uint4*)&Vs[sub * FKSUB + tg * FKSLAB
                                              + (db * 8 + g) * 4];
                int s0 = 2 * sub, s1 = s0 + 1;
                mmaf16(oacc[db], a0[s0], a1[s0], a2[s0], a3[s0], vf.x, vf.y);
                mmaf16(oacc[db], a0[s1], a1[s1], a2[s1], a3[s1], vf.z, vf.w);
            }
    }

    float iA = 1.f / l0, iB = 1.f / l1;
#pragma unroll
    for (int db = 0; db < 8; db++) {
        int c = db * 8 + 2 * tg;
        *(float2*)(O + baseQ + (size_t)(row0 + rA) * EMB + c) =
            make_float2(oacc[db][0] * iA, oacc[db][1] * iA);
        *(float2*)(O + baseQ + (size_t)(row0 + rB) * EMB + c) =
            make_float2(oacc[db][2] * iB, oacc[db][3] * iB);
    }
}

// ======================= host orchestration =================================
extern "C" void kernel_launch(void* const* d_in, const int* in_sizes, int n_in,
                              void* d_out, int out_size) {
    const float* x     = (const float*)d_in[0];
    const float* Wq    = (const float*)d_in[1];
    const float* Wk    = (const float*)d_in[2];
    const float* Wv    = (const float*)d_in[3];
    const float* Wproj = (const float*)d_in[4];
    const float* bproj = (const float*)d_in[5];
    const float* W1    = (const float*)d_in[6];
    const float* b1    = (const float*)d_in[7];
    const float* W2    = (const float*)d_in[8];
    const float* b2    = (const float*)d_in[9];
    const float* g1    = (const float*)d_in[10];
    const float* be1   = (const float*)d_in[11];
    const float* g2    = (const float*)d_in[12];
    const float* be2   = (const float*)d_in[13];
    float* out = (float*)d_out;

    void *ph, *pq, *pk, *pv, *pvt, *pattn, *px1, *pffn;
    void *pwq, *pwk, *pwv, *pwp, *pw1, *pw2;
    cudaGetSymbolAddress(&ph,    g_h);
    cudaGetSymbolAddress(&pq,    g_q);
    cudaGetSymbolAddress(&pk,    g_k);
    cudaGetSymbolAddress(&pv,    g_v);
    cudaGetSymbolAddress(&pvt,   g_vt);
    cudaGetSymbolAddress(&pattn, g_attn);
    cudaGetSymbolAddress(&px1,   g_x1);
    cudaGetSymbolAddress(&pffn,  g_ffn);
    cudaGetSymbolAddress(&pwq,   g_wqt);
    cudaGetSymbolAddress(&pwk,   g_wkt);
    cudaGetSymbolAddress(&pwv,   g_wvt);
    cudaGetSymbolAddress(&pwp,   g_wpt);
    cudaGetSymbolAddress(&pw1,   g_w1t);
    cudaGetSymbolAddress(&pw2,   g_w2t);
    float* f_h    = (float*)ph;
    float* f_q    = (float*)pq;
    float* f_k    = (float*)pk;
    float* f_v    = (float*)pv;
    float* f_vt   = (float*)pvt;
    float* f_attn = (float*)pattn;
    float* f_x1   = (float*)px1;
    float* f_ffn  = (float*)pffn;

    dim3 tb(32, 8);
    dim3 gP(EMB / 128, ROWS / 128);     // (8, 32)
    dim3 gF1(FFDIM / 128, ROWS / 128);  // (32, 32)

    // Launch order arranged so launch #6 (ncu -s 5 -c 1) is a gemm_mma.
    ln_kernel<<<ROWS, 256>>>(x, g1, be1, f_h);                              // 1
    transpose_w<<<dim3(EMB / 32, EMB / 32), tb>>>(Wq, (float*)pwq, EMB, EMB, 1); // 2
    transpose_w<<<dim3(EMB / 32, EMB / 32), tb>>>(Wk, (float*)pwk, EMB, EMB, 1); // 3
    transpose_w<<<dim3(EMB / 32, EMB / 32), tb>>>(Wv, (float*)pwv, EMB, EMB, 1); // 4
    transpose_w<<<dim3(EMB / 32, EMB / 32), tb>>>(Wproj, (float*)pwp, EMB, EMB, 0); // 5

    gemm_mma<<<gP, 256>>>(f_h, (float*)pwq, f_q, nullptr, nullptr, 0, EMB, EMB);  // 6 <- ncu
    gemm_mma<<<gP, 256>>>(f_h, (float*)pwk, f_k, nullptr, nullptr, 0, EMB, EMB);  // 7
    gemm_mma<<<gP, 256>>>(f_h, (float*)pwv, f_v, nullptr, nullptr, 0, EMB, EMB);  // 8

    transpose_v<<<dim3(SEQ / 32, DHEAD / 32, 32), tb>>>(f_v, f_vt);         // 9
    flash_mma<<<dim3(SEQ / 128, 32), 256>>>(f_q, f_k, f_vt, f_attn);        // 10

    gemm_mma<<<gP, 256>>>(f_attn, (float*)pwp, f_x1, bproj, x, 0, EMB, EMB); // 11
    ln_kernel<<<ROWS, 256>>>(f_x1, g2, be2, f_h);                            // 12

    transpose_w<<<dim3(FFDIM / 32, EMB / 32), tb>>>(W1, (float*)pw1, EMB, FFDIM, 0); // 13
    transpose_w<<<dim3(EMB / 32, FFDIM / 32), tb>>>(W2, (float*)pw2, FFDIM, EMB, 0); // 14

    gemm_mma<<<gF1, 256>>>(f_h, (float*)pw1, f_ffn, b1, nullptr, 1, EMB, FFDIM);   // 15
    gemm_mma<<<gP, 256>>>(f_ffn, (float*)pw2, out, b2, f_x1, 0, FFDIM, EMB);       // 16
}

// round 7
// speedup vs baseline: 4.1390x; 1.5097x over previous
#include <cuda_runtime.h>
#include <cuda_fp16.h>
#include <cstdint>
#include <cstddef>

// Problem constants
#define BATCH 2
#define SEQ   2048
#define EMB   1024
#define HEADS 16
#define DHEAD 64
#define ROWS  (BATCH*SEQ)          // 4096
#define FFDIM (4*EMB)              // 4096

// ---------------- scratch (allocation-free: __device__ globals) ----------------
// fp16 activations / weights stored as ushort arrays (avoid __half static-init issues)
__device__ unsigned short g_h   [ROWS*EMB];
__device__ unsigned short g_q   [ROWS*EMB];
__device__ unsigned short g_k   [ROWS*EMB];
__device__ unsigned short g_v   [ROWS*EMB];
__device__ unsigned short g_vt  [32*DHEAD*SEQ];   // V transposed: [bh][d][s]
__device__ unsigned short g_attn[ROWS*EMB];
__device__ unsigned short g_ffn [ROWS*FFDIM];
__device__ float          g_x1  [ROWS*EMB];
// transposed weights, [N, K] K-major, fp16
__device__ unsigned short g_wqt [EMB*EMB];
__device__ unsigned short g_wkt [EMB*EMB];
__device__ unsigned short g_wvt [EMB*EMB];
__device__ unsigned short g_wpt [EMB*EMB];
__device__ unsigned short g_w1t [EMB*FFDIM];
__device__ unsigned short g_w2t [FFDIM*EMB];

// ======================= fp16 mma helpers ====================================
__device__ __forceinline__ uint32_t packh2(float lo, float hi) {
    __half2 h = __floats2half2_rn(lo, hi);
    return *reinterpret_cast<uint32_t*>(&h);
}
__device__ __forceinline__ void mmaf16(float* c,
                                       uint32_t a0, uint32_t a1,
                                       uint32_t a2, uint32_t a3,
                                       uint32_t b0, uint32_t b1) {
    asm volatile(
        "mma.sync.aligned.m16n8k16.row.col.f32.f16.f16.f32 "
        "{%0,%1,%2,%3}, {%4,%5,%6,%7}, {%8,%9}, {%0,%1,%2,%3};"
        : "+f"(c[0]), "+f"(c[1]), "+f"(c[2]), "+f"(c[3])
        : "r"(a0), "r"(a1), "r"(a2), "r"(a3), "r"(b0), "r"(b1));
}

// ======================= tensor-core fp16 GEMM ===============================
// C[M,N] = A[M,K]*Bt[N,K]^T, fp16 in / fp32 accum. A,B fp16 in global.
// BM=BN=128, BK=32 half-elements (16 half2 units/row). 256 thr, 8 warps (2x4).
// Smem unit layout: S[(u&3)*520 + row*4 + (u>>2)]  (validated R6 mapping).
// 2-deep LDG register pipeline, manually unrolled x2 (static reg sets).
#define GSLAB 520

__global__ void __launch_bounds__(256, 1)
gemm_mma(const __half* __restrict__ A, const __half* __restrict__ Bt,
         void* __restrict__ Cv,
         const float* __restrict__ bias,
         const float* __restrict__ residual,
         int doRelu, int K, int N, int halfOut) {
    __shared__ uint32_t As[2][4 * GSLAB];
    __shared__ uint32_t Bs[2][4 * GSLAB];
    int t = threadIdx.x;
    int lane = t & 31, wid = t >> 5;
    int g = lane >> 2, tg = lane & 3;
    int warp_m = wid & 1, warp_n = wid >> 1;
    int m0 = blockIdx.y * 128, n0 = blockIdx.x * 128;

    int row_ld = t >> 1, ub = (t & 1) * 8;
    const __half* Arow = A  + (size_t)(m0 + row_ld) * K;
    const __half* Brow = Bt + (size_t)(n0 + row_ld) * K;

    float acc[4][4][4];
#pragma unroll
    for (int i = 0; i < 4; i++)
#pragma unroll
        for (int j = 0; j < 4; j++)
#pragma unroll
            for (int r = 0; r < 4; r++) acc[i][j][r] = 0.f;

    uint4 a00, a01, b00, b01;   // register set 0
    uint4 a10, a11, b10, b11;   // register set 1

#define LDGK(aX, aY, bX, bY, k0)                                        \
    do {                                                                \
        const uint4* pa_ = (const uint4*)(Arow + (k0)) + ((t & 1) << 1);\
        const uint4* pb_ = (const uint4*)(Brow + (k0)) + ((t & 1) << 1);\
        aX = pa_[0]; aY = pa_[1]; bX = pb_[0]; bY = pb_[1];             \
    } while (0)

#define STSK(aX, aY, bX, bY, buf)                                       \
    do {                                                                \
        uint32_t av_[8] = {aX.x, aX.y, aX.z, aX.w, aY.x, aY.y, aY.z, aY.w}; \
        uint32_t bv_[8] = {bX.x, bX.y, bX.z, bX.w, bY.x, bY.y, bY.z, bY.w}; \
        _Pragma("unroll")                                               \
        for (int j = 0; j < 8; j++) {                                   \
            int u = ub + j;                                             \
            int off = (u & 3) * GSLAB + row_ld * 4 + (u >> 2);          \
            As[buf][off] = av_[j];                                      \
            Bs[buf][off] = bv_[j];                                      \
        }                                                               \
    } while (0)

#define TILE_MMA(buf)                                                   \
    do {                                                                \
        uint4 a0f[4], a8f[4], bff[4];                                   \
        _Pragma("unroll")                                               \
        for (int mf = 0; mf < 4; mf++) {                                \
            int row = warp_m * 64 + mf * 16 + g;                        \
            a0f[mf] = *(const uint4*)&As[buf][tg * GSLAB + row * 4];    \
            a8f[mf] = *(const uint4*)&As[buf][tg * GSLAB + (row + 8) * 4]; \
        }                                                               \
        _Pragma("unroll")                                               \
        for (int nf = 0; nf < 4; nf++) {                                \
            int n = warp_n * 32 + nf * 8 + g;                           \
            bff[nf] = *(const uint4*)&Bs[buf][tg * GSLAB + n * 4];      \
        }                                                               \
        _Pragma("unroll")                                               \
        for (int mf = 0; mf < 4; mf++)                                  \
            _Pragma("unroll")                                           \
            for (int nf = 0; nf < 4; nf++) {                            \
                mmaf16(acc[mf][nf], a0f[mf].x, a8f[mf].x,               \
                       a0f[mf].y, a8f[mf].y, bff[nf].x, bff[nf].y);     \
                mmaf16(acc[mf][nf], a0f[mf].z, a8f[mf].z,               \
                       a0f[mf].w, a8f[mf].w, bff[nf].z, bff[nf].w);     \
            }                                                           \
    } while (0)

    int NKt = K >> 5;    // BK = 32 half elements; NKt is even (K = 1024/4096)

    LDGK(a00, a01, b00, b01, 0);
    LDGK(a10, a11, b10, b11, 32);
    STSK(a00, a01, b00, b01, 0);
    __syncthreads();

    for (int it = 0; it < NKt; it += 2) {
        // even sub-iter: consume buf0; prefetch tile it+2 into set0; stage tile it+1
        if (it + 2 < NKt) LDGK(a00, a01, b00, b01, (it + 2) << 5);
        TILE_MMA(0);
        STSK(a10, a11, b10, b11, 1);
        __syncthreads();
        // odd sub-iter: consume buf1; prefetch tile it+3 into set1; stage tile it+2
        if (it + 3 < NKt) LDGK(a10, a11, b10, b11, (it + 3) << 5);
        TILE_MMA(1);
        if (it + 2 < NKt) STSK(a00, a01, b00, b01, 0);
        __syncthreads();
    }

    // epilogue
#pragma unroll
    for (int mf = 0; mf < 4; mf++) {
#pragma unroll
        for (int nf = 0; nf < 4; nf++) {
            int row = m0 + warp_m * 64 + mf * 16 + g;
            int col = n0 + warp_n * 32 + nf * 8 + 2 * tg;
            float b0 = 0.f, b1 = 0.f;
            if (bias) { b0 = bias[col]; b1 = bias[col + 1]; }
#pragma unroll
            for (int rr = 0; rr < 2; rr++) {
                int r = row + rr * 8;
                float v0 = acc[mf][nf][rr * 2 + 0] + b0;
                float v1 = acc[mf][nf][rr * 2 + 1] + b1;
                if (doRelu) { v0 = fmaxf(v0, 0.f); v1 = fmaxf(v1, 0.f); }
                if (residual) {
                    float2 rv = *(const float2*)(residual + (size_t)r * N + col);
                    v0 += rv.x; v1 += rv.y;
                }
                if (halfOut) {
                    *(uint32_t*)((__half*)Cv + (size_t)r * N + col) = packh2(v0, v1);
                } else {
                    *(float2*)((float*)Cv + (size_t)r * N + col) = make_float2(v0, v1);
                }
            }
        }
    }
}

// ======================= weight transpose (fp32 in -> fp16 out) ==============
__global__ void transpose_w(const float* __restrict__ in, __half* __restrict__ out,
                            int K, int N, int headMode) {
    __shared__ float tile[32][33];
    int k0 = blockIdx.y * 32, n0 = blockIdx.x * 32;
    int tx = threadIdx.x, ty = threadIdx.y;
    for (int i = ty; i < 32; i += 8) {
        int k = k0 + i, n = n0 + tx;
        float v = headMode
            ? in[(size_t)(n >> 6) * K * 64 + (size_t)k * 64 + (n & 63)]
            : in[(size_t)k * N + n];
        tile[i][tx] = v;
    }
    __syncthreads();
    for (int i = ty; i < 32; i += 8) {
        out[(size_t)(n0 + i) * K + k0 + tx] = __float2half(tile[tx][i]);
    }
}

// ======================= V transpose (fp16): [b,s,h*64+d] -> [bh][d][s] ======
__global__ void transpose_v(const unsigned short* __restrict__ v,
                            unsigned short* __restrict__ vt) {
    __shared__ unsigned short tile[32][33];
    int bh = blockIdx.z;
    int s0 = blockIdx.x * 32, d0 = blockIdx.y * 32;
    int b = bh >> 4, h = bh & 15;
    int tx = threadIdx.x, ty = threadIdx.y;
    for (int i = ty; i < 32; i += 8)
        tile[i][tx] = v[(size_t)(b * SEQ + s0 + i) * EMB + h * 64 + d0 + tx];
    __syncthreads();
    for (int i = ty; i < 32; i += 8)
        vt[((size_t)bh * 64 + d0 + i) * SEQ + s0 + tx] = tile[tx][i];
}

// ======================= LayerNorm (fp32 in -> fp16 out) =====================
__global__ void ln_kernel(const float* __restrict__ x,
                          const float* __restrict__ g,
                          const float* __restrict__ b,
                          __half* __restrict__ out) {
    int row = blockIdx.x;
    const float* xr = x + (size_t)row * EMB;
    float v[4];
    float s = 0.f, ss = 0.f;
#pragma unroll
    for (int i = 0; i < 4; i++) {
        v[i] = xr[threadIdx.x + i * 256];
        s += v[i]; ss += v[i] * v[i];
    }
#pragma unroll
    for (int m = 16; m; m >>= 1) {
        s  += __shfl_xor_sync(0xffffffffu, s,  m);
        ss += __shfl_xor_sync(0xffffffffu, ss, m);
    }
    __shared__ float red[2][8];
    int warp = threadIdx.x >> 5, lane = threadIdx.x & 31;
    if (lane == 0) { red[0][warp] = s; red[1][warp] = ss; }
    __syncthreads();
    float S = 0.f, SS = 0.f;
#pragma unroll
    for (int w = 0; w < 8; w++) { S += red[0][w]; SS += red[1][w]; }
    float mean = S * (1.f / EMB);
    float var  = SS * (1.f / EMB) - mean * mean;
    float inv  = rsqrtf(var + 1e-5f);
    __half* orow = out + (size_t)row * EMB;
#pragma unroll
    for (int i = 0; i < 4; i++) {
        int e = threadIdx.x + i * 256;
        orow[e] = __float2half((v[i] - mean) * inv * g[e] + b[e]);
    }
}

// ======================= Flash attention, fp16 tensor cores ==================
// Br=128 (8 warps x 16 rows), Bc=64, d=64; all operands fp16; P in registers.
// Smem unit layout (unit = half2): identical structure to validated R6.
//   Q (128 rows, 32 units): sub*2080 + (uu&3)*520 + r*4 + (uu>>2)
//   K/V (64 rows, 32 units): sub*1056 + (uu&3)*264 + r*4 + (uu>>2)
#define FQSLAB 520
#define FKSLAB 264
#define FQSUB  2080
#define FKSUB  1056

__global__ void __launch_bounds__(256)
flash_mma(const __half* __restrict__ Q, const __half* __restrict__ Kg,
          const __half* __restrict__ Vt, __half* __restrict__ O) {
    __shared__ uint32_t Qs[2 * FQSUB];
    __shared__ uint32_t Ks[2 * FKSUB];
    __shared__ uint32_t Vs[2 * FKSUB];
    int t = threadIdx.x, lane = t & 31, w = t >> 5;
    int g = lane >> 2, tg = lane & 3;
    int bh = blockIdx.y;
    int row0 = blockIdx.x * 128;
    size_t baseQ = (size_t)(bh >> 4) * SEQ * EMB + (size_t)(bh & 15) * DHEAD;
    size_t baseV = (size_t)bh * DHEAD * SEQ;
    const __half2 qscale = __float2half2_rn(0.125f);   // 2^-3, exact

    // load Q tile (scale by 2^-3 in fp16, exact)
    for (int i = t; i < 1024; i += 256) {
        int r = i >> 3, q = i & 7;
        uint4 p = *(const uint4*)(Q + baseQ + (size_t)(row0 + r) * EMB + q * 8);
        uint32_t un[4] = {p.x, p.y, p.z, p.w};
#pragma unroll
        for (int jj = 0; jj < 4; jj++) {
            __half2 hv = *reinterpret_cast<__half2*>(&un[jj]);
            hv = __hmul2(hv, qscale);
            int u = q * 4 + jj;
            int s_ = u >> 4, uu = u & 15;
            Qs[s_ * FQSUB + (uu & 3) * FQSLAB + r * 4 + (uu >> 2)]
                = *reinterpret_cast<uint32_t*>(&hv);
        }
    }
    __syncthreads();

    int rA = w * 16 + g, rB = rA + 8;
    uint4 qfA[2], qfB[2];
#pragma unroll
    for (int sub = 0; sub < 2; sub++) {
        qfA[sub] = *(const uint4*)&Qs[sub * FQSUB + tg * FQSLAB + rA * 4];
        qfB[sub] = *(const uint4*)&Qs[sub * FQSUB + tg * FQSLAB + rB * 4];
    }

    float m0 = -1e30f, m1 = -1e30f, l0 = 0.f, l1 = 0.f;
    float oacc[8][4];
#pragma unroll
    for (int i = 0; i < 8; i++)
#pragma unroll
        for (int j = 0; j < 4; j++) oacc[i][j] = 0.f;

    for (int kt = 0; kt < SEQ; kt += 64) {
        __syncthreads();   // prior iteration done reading Ks/Vs
#pragma unroll
        for (int ii = 0; ii < 2; ii++) {
            int i = t + ii * 256;
            int r = i >> 3, q = i & 7;
            uint4 pk = *(const uint4*)(Kg + baseQ + (size_t)(kt + r) * EMB + q * 8);
            uint4 pv = *(const uint4*)(Vt + baseV + (size_t)r * SEQ + kt + q * 8);
            uint32_t ku[4] = {pk.x, pk.y, pk.z, pk.w};
            uint32_t vu[4] = {pv.x, pv.y, pv.z, pv.w};
#pragma unroll
            for (int jj = 0; jj < 4; jj++) {
                int u = q * 4 + jj;
                int s_ = u >> 4, uu = u & 15;
                int off = s_ * FKSUB + (uu & 3) * FKSLAB + r * 4 + (uu >> 2);
                Ks[off] = ku[jj];
                Vs[off] = vu[jj];
            }
        }
        __syncthreads();

        // S = Q K^T : 16x64 per warp
        float sacc[8][4];
#pragma unroll
        for (int i = 0; i < 8; i++)
#pragma unroll
            for (int j = 0; j < 4; j++) sacc[i][j] = 0.f;
#pragma unroll
        for (int sub = 0; sub < 2; sub++) {
            uint4 qa = qfA[sub], qb = qfB[sub];
#pragma unroll
            for (int nb = 0; nb < 8; nb++) {
                uint4 kf = *(const uint4*)&Ks[sub * FKSUB + tg * FKSLAB
                                              + (nb * 8 + g) * 4];
                mmaf16(sacc[nb], qa.x, qb.x, qa.y, qb.y, kf.x, kf.y);
                mmaf16(sacc[nb], qa.z, qb.z, qa.w, qb.w, kf.z, kf.w);
            }
        }

        // online softmax
        float mxA = -1e30f, mxB = -1e30f;
#pragma unroll
        for (int nb = 0; nb < 8; nb++) {
            mxA = fmaxf(mxA, fmaxf(sacc[nb][0], sacc[nb][1]));
            mxB = fmaxf(mxB, fmaxf(sacc[nb][2], sacc[nb][3]));
        }
        mxA = fmaxf(mxA, __shfl_xor_sync(0xffffffffu, mxA, 1));
        mxA = fmaxf(mxA, __shfl_xor_sync(0xffffffffu, mxA, 2));
        mxB = fmaxf(mxB, __shfl_xor_sync(0xffffffffu, mxB, 1));
        mxB = fmaxf(mxB, __shfl_xor_sync(0xffffffffu, mxB, 2));
        float mnA = fmaxf(m0, mxA), mnB = fmaxf(m1, mxB);
        float cA = __expf(m0 - mnA), cB = __expf(m1 - mnB);
        m0 = mnA; m1 = mnB;
        float rsA = 0.f, rsB = 0.f;
#pragma unroll
        for (int nb = 0; nb < 8; nb++) {
            sacc[nb][0] = __expf(sacc[nb][0] - mnA);
            sacc[nb][1] = __expf(sacc[nb][1] - mnA);
            sacc[nb][2] = __expf(sacc[nb][2] - mnB);
            sacc[nb][3] = __expf(sacc[nb][3] - mnB);
            rsA += sacc[nb][0] + sacc[nb][1];
            rsB += sacc[nb][2] + sacc[nb][3];
        }
        rsA += __shfl_xor_sync(0xffffffffu, rsA, 1);
        rsA += __shfl_xor_sync(0xffffffffu, rsA, 2);
        rsB += __shfl_xor_sync(0xffffffffu, rsB, 1);
        rsB += __shfl_xor_sync(0xffffffffu, rsB, 2);
        l0 = l0 * cA + rsA;
        l1 = l1 * cB + rsB;
#pragma unroll
        for (int db = 0; db < 8; db++) {
            oacc[db][0] *= cA; oacc[db][1] *= cA;
            oacc[db][2] *= cB; oacc[db][3] *= cB;
        }

        // pack P into registers (fragment-exact)
        uint32_t a0[4], a1[4], a2[4], a3[4];
#pragma unroll
        for (int s = 0; s < 4; s++) {
            a0[s] = packh2(sacc[2 * s][0],     sacc[2 * s][1]);
            a1[s] = packh2(sacc[2 * s][2],     sacc[2 * s][3]);
            a2[s] = packh2(sacc[2 * s + 1][0], sacc[2 * s + 1][1]);
            a3[s] = packh2(sacc[2 * s + 1][2], sacc[2 * s + 1][3]);
        }

        // O += P V
#pragma unroll
        for (int db = 0; db < 8; db++)
#pragma unroll
            for (int sub = 0; sub < 2; sub++) {
                uint4 vf = *(const uint4*)&Vs[sub * FKSUB + tg * FKSLAB
                                              + (db * 8 + g) * 4];
                int s0 = 2 * sub, s1 = s0 + 1;
                mmaf16(oacc[db], a0[s0], a1[s0], a2[s0], a3[s0], vf.x, vf.y);
                mmaf16(oacc[db], a0[s1], a1[s1], a2[s1], a3[s1], vf.z, vf.w);
            }
    }

    float iA = 1.f / l0, iB = 1.f / l1;
#pragma unroll
    for (int db = 0; db < 8; db++) {
        int c = db * 8 + 2 * tg;
        *(uint32_t*)(O + baseQ + (size_t)(row0 + rA) * EMB + c) =
            packh2(oacc[db][0] * iA, oacc[db][1] * iA);
        *(uint32_t*)(O + baseQ + (size_t)(row0 + rB) * EMB + c) =
            packh2(oacc[db][2] * iB, oacc[db][3] * iB);
    }
}

// ======================= host orchestration =================================
extern "C" void kernel_launch(void* const* d_in, const int* in_sizes, int n_in,
                              void* d_out, int out_size) {
    const float* x     = (const float*)d_in[0];
    const float* Wq    = (const float*)d_in[1];
    const float* Wk    = (const float*)d_in[2];
    const float* Wv    = (const float*)d_in[3];
    const float* Wproj = (const float*)d_in[4];
    const float* bproj = (const float*)d_in[5];
    const float* W1    = (const float*)d_in[6];
    const float* b1    = (const float*)d_in[7];
    const float* W2    = (const float*)d_in[8];
    const float* b2    = (const float*)d_in[9];
    const float* g1    = (const float*)d_in[10];
    const float* be1   = (const float*)d_in[11];
    const float* g2    = (const float*)d_in[12];
    const float* be2   = (const float*)d_in[13];
    float* out = (float*)d_out;

    void *ph, *pq, *pk, *pv, *pvt, *pattn, *px1, *pffn;
    void *pwq, *pwk, *pwv, *pwp, *pw1, *pw2;
    cudaGetSymbolAddress(&ph,    g_h);
    cudaGetSymbolAddress(&pq,    g_q);
    cudaGetSymbolAddress(&pk,    g_k);
    cudaGetSymbolAddress(&pv,    g_v);
    cudaGetSymbolAddress(&pvt,   g_vt);
    cudaGetSymbolAddress(&pattn, g_attn);
    cudaGetSymbolAddress(&px1,   g_x1);
    cudaGetSymbolAddress(&pffn,  g_ffn);
    cudaGetSymbolAddress(&pwq,   g_wqt);
    cudaGetSymbolAddress(&pwk,   g_wkt);
    cudaGetSymbolAddress(&pwv,   g_wvt);
    cudaGetSymbolAddress(&pwp,   g_wpt);
    cudaGetSymbolAddress(&pw1,   g_w1t);
    cudaGetSymbolAddress(&pw2,   g_w2t);
    __half* f_h    = (__half*)ph;
    __half* f_q    = (__half*)pq;
    __half* f_k    = (__half*)pk;
    __half* f_v    = (__half*)pv;
    __half* f_vt   = (__half*)pvt;
    __half* f_attn = (__half*)pattn;
    float*  f_x1   = (float*)px1;
    __half* f_ffn  = (__half*)pffn;

    dim3 tb(32, 8);
    dim3 gP(EMB / 128, ROWS / 128);     // (8, 32)
    dim3 gF1(FFDIM / 128, ROWS / 128);  // (32, 32)

    ln_kernel<<<ROWS, 256>>>(x, g1, be1, f_h);
    transpose_w<<<dim3(EMB / 32, EMB / 32), tb>>>(Wq, (__half*)pwq, EMB, EMB, 1);
    transpose_w<<<dim3(EMB / 32, EMB / 32), tb>>>(Wk, (__half*)pwk, EMB, EMB, 1);
    transpose_w<<<dim3(EMB / 32, EMB / 32), tb>>>(Wv, (__half*)pwv, EMB, EMB, 1);
    transpose_w<<<dim3(EMB / 32, EMB / 32), tb>>>(Wproj, (__half*)pwp, EMB, EMB, 0);

    // QKV projections: M=4096, N=1024, K=1024 (half out)
    gemm_mma<<<gP, 256>>>(f_h, (__half*)pwq, f_q, nullptr, nullptr, 0, EMB, EMB, 1);
    gemm_mma<<<gP, 256>>>(f_h, (__half*)pwk, f_k, nullptr, nullptr, 0, EMB, EMB, 1);
    gemm_mma<<<gP, 256>>>(f_h, (__half*)pwv, f_v, nullptr, nullptr, 0, EMB, EMB, 1);

    transpose_v<<<dim3(SEQ / 32, DHEAD / 32, 32), tb>>>(
        (const unsigned short*)pv, (unsigned short*)pvt);
    flash_mma<<<dim3(SEQ / 128, 32), 256>>>(f_q, f_k, f_vt, f_attn);

    // x1 = x + attn @ Wproj + bproj  (fp32 out)
    gemm_mma<<<gP, 256>>>(f_attn, (__half*)pwp, f_x1, bproj, x, 0, EMB, EMB, 0);
    ln_kernel<<<ROWS, 256>>>(f_x1, g2, be2, f_h);

    transpose_w<<<dim3(FFDIM / 32, EMB / 32), tb>>>(W1, (__half*)pw1, EMB, FFDIM, 0);
    transpose_w<<<dim3(EMB / 32, FFDIM / 32), tb>>>(W2, (__half*)pw2, FFDIM, EMB, 0);

    // ffn hidden = relu(h2 @ W1 + b1)  (half out)
    gemm_mma<<<gF1, 256>>>(f_h, (__half*)pw1, f_ffn, b1, nullptr, 1, EMB, FFDIM, 1);
    // out = x1 + hidden @ W2 + b2  (fp32 out)
    gemm_mma<<<gP, 256>>>(f_ffn, (__half*)pw2, out, b2, f_x1, 0, FFDIM, EMB, 0);
}

// round 8
// speedup vs baseline: 5.0515x; 1.2205x over previous
#include <cuda_runtime.h>
#include <cuda_fp16.h>
#include <cstdint>
#include <cstddef>

// Problem constants
#define BATCH 2
#define SEQ   2048
#define EMB   1024
#define HEADS 16
#define DHEAD 64
#define ROWS  (BATCH*SEQ)          // 4096
#define FFDIM (4*EMB)              // 4096

// ---------------- scratch (allocation-free: __device__ globals) ----------------
__device__ unsigned short g_h   [ROWS*EMB];
__device__ unsigned short g_q   [ROWS*EMB];
__device__ unsigned short g_k   [ROWS*EMB];
__device__ unsigned short g_v   [ROWS*EMB];
__device__ unsigned short g_vt  [32*DHEAD*SEQ];   // V transposed: [bh][d][s]
__device__ unsigned short g_attn[ROWS*EMB];
__device__ unsigned short g_ffn [ROWS*FFDIM];
__device__ float          g_x1  [ROWS*EMB];
// transposed weights, [N, K] K-major, fp16
__device__ unsigned short g_wqt [EMB*EMB];
__device__ unsigned short g_wkt [EMB*EMB];
__device__ unsigned short g_wvt [EMB*EMB];
__device__ unsigned short g_wpt [EMB*EMB];
__device__ unsigned short g_w1t [EMB*FFDIM];
__device__ unsigned short g_w2t [FFDIM*EMB];

// ======================= PTX helpers =========================================
__device__ __forceinline__ uint32_t smem_u32(const void* p) {
    uint32_t a;
    asm("{ .reg .u64 t; cvta.to.shared.u64 t, %1; cvt.u32.u64 %0, t; }"
        : "=r"(a) : "l"(p));
    return a;
}
#define CP_ASYNC16(dst, src) \
    asm volatile("cp.async.cg.shared.global [%0], [%1], 16;" \
                 :: "r"(dst), "l"(src) : "memory")
#define CP_COMMIT() asm volatile("cp.async.commit_group;" ::: "memory")
#define CP_WAIT1()  asm volatile("cp.async.wait_group 1;"  ::: "memory")
__device__ __forceinline__ void ldmx4(uint32_t* r, uint32_t addr) {
    asm volatile("ldmatrix.sync.aligned.m8n8.x4.shared.b16 {%0,%1,%2,%3}, [%4];"
                 : "=r"(r[0]), "=r"(r[1]), "=r"(r[2]), "=r"(r[3]) : "r"(addr));
}
__device__ __forceinline__ uint32_t packh2(float lo, float hi) {
    __half2 h = __floats2half2_rn(lo, hi);
    return *reinterpret_cast<uint32_t*>(&h);
}
__device__ __forceinline__ void mmaf16(float* c,
                                       uint32_t a0, uint32_t a1,
                                       uint32_t a2, uint32_t a3,
                                       uint32_t b0, uint32_t b1) {
    asm volatile(
        "mma.sync.aligned.m16n8k16.row.col.f32.f16.f16.f32 "
        "{%0,%1,%2,%3}, {%4,%5,%6,%7}, {%8,%9}, {%0,%1,%2,%3};"
        : "+f"(c[0]), "+f"(c[1]), "+f"(c[2]), "+f"(c[3])
        : "r"(a0), "r"(a1), "r"(a2), "r"(a3), "r"(b0), "r"(b1));
}

// ======================= tensor-core fp16 GEMM (cp.async + ldmatrix) =========
// C[M,N] = A[M,K]*Bt[N,K]^T, fp16 in / fp32 accum.
// BM=BN=128, BK=64 halves (128B/row, 8 x 16B units), XOR-8 swizzle col^(row&7).
// 3-stage cp.async ring; 256 thr, 8 warps (2x4), 64x32 per warp.
#define G_STAGE 32768              // A 16KB + B 16KB
#define G_SMEM  (3 * G_STAGE)      // 98304

__global__ void __launch_bounds__(256)
gemm_mma(const __half* __restrict__ A, const __half* __restrict__ Bt,
         void* __restrict__ Cv,
         const float* __restrict__ bias,
         const float* __restrict__ residual,
         int doRelu, int K, int N, int halfOut) {
    extern __shared__ __align__(128) char smem[];
    uint32_t sbase = smem_u32(smem);
    int t = threadIdx.x;
    int lane = t & 31, wid = t >> 5;
    int g = lane >> 2, tg = lane & 3;
    int warp_m = wid & 1, warp_n = wid >> 1;
    int m0 = blockIdx.y * 128, n0 = blockIdx.x * 128;

    // cp.async assignment: thread t -> row t>>1, units (t&1)*4 .. +3
    int ld_row = t >> 1, ld_c0 = (t & 1) * 4;
    const __half* Arow = A  + (size_t)(m0 + ld_row) * K;
    const __half* Brow = Bt + (size_t)(n0 + ld_row) * K;
    int ld_swz = ld_row & 7;
    uint32_t ld_off = (uint32_t)ld_row * 128;

    // ldmatrix per-lane geometry
    int sub = lane >> 3, r_in = lane & 7;
    // A: row = warp_m*64 + mf*16 + (sub&1)*8 + r_in ; unit u = 2*ks + (sub>>1)
    uint32_t a_row[4], a_swz[4];
#pragma unroll
    for (int mf = 0; mf < 4; mf++) {
        int r = warp_m * 64 + mf * 16 + (sub & 1) * 8 + r_in;
        a_row[mf] = (uint32_t)r * 128;
        a_swz[mf] = (uint32_t)(r & 7);
    }
    int a_du = sub >> 1;
    // B: row = warp_n*32 + nf*8 + r_in ; unit u = kp*4 + sub
    uint32_t b_row[4], b_swz[4];
#pragma unroll
    for (int nf = 0; nf < 4; nf++) {
        int r = warp_n * 32 + nf * 8 + r_in;
        b_row[nf] = (uint32_t)r * 128;
        b_swz[nf] = (uint32_t)(r & 7);
    }

    float acc[4][4][4];
#pragma unroll
    for (int i = 0; i < 4; i++)
#pragma unroll
        for (int j = 0; j < 4; j++)
#pragma unroll
            for (int r = 0; r < 4; r++) acc[i][j][r] = 0.f;

#define G_ISSUE(s, k0)                                                        \
    do {                                                                      \
        uint32_t ab_ = sbase + (s) * G_STAGE + ld_off;                        \
        uint32_t bb_ = ab_ + 16384;                                           \
        _Pragma("unroll")                                                     \
        for (int j = 0; j < 4; j++) {                                         \
            int c_ = ld_c0 + j;                                               \
            uint32_t cp_ = (uint32_t)(c_ ^ ld_swz) * 16;                      \
            CP_ASYNC16(ab_ + cp_, Arow + (k0) + c_ * 8);                      \
            CP_ASYNC16(bb_ + cp_, Brow + (k0) + c_ * 8);                      \
        }                                                                     \
    } while (0)

    int NKt = K >> 6;   // K = 1024 or 4096 -> 16 / 64 tiles
    G_ISSUE(0, 0);  CP_COMMIT();
    G_ISSUE(1, 64); CP_COMMIT();

    int s = 0;
    for (int it = 0; it < NKt; it++) {
        CP_WAIT1();
        __syncthreads();
        int snext = (s == 2) ? 0 : s + 1;
        int sfill = (snext == 2) ? 0 : snext + 1;
        if (it + 2 < NKt) G_ISSUE(sfill, (it + 2) << 6);
        CP_COMMIT();

        uint32_t abase = sbase + s * G_STAGE;
        uint32_t bbase = abase + 16384;
#pragma unroll
        for (int kp = 0; kp < 2; kp++) {
            uint32_t bfr[4][4];
#pragma unroll
            for (int nf = 0; nf < 4; nf++) {
                uint32_t u = (uint32_t)(kp * 4 + sub) ^ b_swz[nf];
                ldmx4(bfr[nf], bbase + b_row[nf] + u * 16);
            }
#pragma unroll
            for (int kss = 0; kss < 2; kss++) {
                int ks = kp * 2 + kss;
                uint32_t afr[4][4];
#pragma unroll
                for (int mf = 0; mf < 4; mf++) {
                    uint32_t u = (uint32_t)(2 * ks + a_du) ^ a_swz[mf];
                    ldmx4(afr[mf], abase + a_row[mf] + u * 16);
                }
#pragma unroll
                for (int mf = 0; mf < 4; mf++)
#pragma unroll
                    for (int nf = 0; nf < 4; nf++)
                        mmaf16(acc[mf][nf],
                               afr[mf][0], afr[mf][1], afr[mf][2], afr[mf][3],
                               bfr[nf][kss * 2], bfr[nf][kss * 2 + 1]);
            }
        }
        s = snext;
    }

    // epilogue (C-fragment layout unchanged)
#pragma unroll
    for (int mf = 0; mf < 4; mf++) {
#pragma unroll
        for (int nf = 0; nf < 4; nf++) {
            int row = m0 + warp_m * 64 + mf * 16 + g;
            int col = n0 + warp_n * 32 + nf * 8 + 2 * tg;
            float b0 = 0.f, b1 = 0.f;
            if (bias) { b0 = bias[col]; b1 = bias[col + 1]; }
#pragma unroll
            for (int rr = 0; rr < 2; rr++) {
                int r = row + rr * 8;
                float v0 = acc[mf][nf][rr * 2 + 0] + b0;
                float v1 = acc[mf][nf][rr * 2 + 1] + b1;
                if (doRelu) { v0 = fmaxf(v0, 0.f); v1 = fmaxf(v1, 0.f); }
                if (residual) {
                    float2 rv = *(const float2*)(residual + (size_t)r * N + col);
                    v0 += rv.x; v1 += rv.y;
                }
                if (halfOut) {
                    *(uint32_t*)((__half*)Cv + (size_t)r * N + col) = packh2(v0, v1);
                } else {
                    *(float2*)((float*)Cv + (size_t)r * N + col) = make_float2(v0, v1);
                }
            }
        }
    }
}

// ======================= weight transpose (fp32 in -> fp16 out) ==============
__global__ void transpose_w(const float* __restrict__ in, __half* __restrict__ out,
                            int K, int N, int headMode) {
    __shared__ float tile[32][33];
    int k0 = blockIdx.y * 32, n0 = blockIdx.x * 32;
    int tx = threadIdx.x, ty = threadIdx.y;
    for (int i = ty; i < 32; i += 8) {
        int k = k0 + i, n = n0 + tx;
        float v = headMode
            ? in[(size_t)(n >> 6) * K * 64 + (size_t)k * 64 + (n & 63)]
            : in[(size_t)k * N + n];
        tile[i][tx] = v;
    }
    __syncthreads();
    for (int i = ty; i < 32; i += 8) {
        out[(size_t)(n0 + i) * K + k0 + tx] = __float2half(tile[tx][i]);
    }
}

// ======================= V transpose (fp16): [b,s,h*64+d] -> [bh][d][s] ======
__global__ void transpose_v(const unsigned short* __restrict__ v,
                            unsigned short* __restrict__ vt) {
    __shared__ unsigned short tile[32][33];
    int bh = blockIdx.z;
    int s0 = blockIdx.x * 32, d0 = blockIdx.y * 32;
    int b = bh >> 4, h = bh & 15;
    int tx = threadIdx.x, ty = threadIdx.y;
    for (int i = ty; i < 32; i += 8)
        tile[i][tx] = v[(size_t)(b * SEQ + s0 + i) * EMB + h * 64 + d0 + tx];
    __syncthreads();
    for (int i = ty; i < 32; i += 8)
        vt[((size_t)bh * 64 + d0 + i) * SEQ + s0 + tx] = tile[tx][i];
}

// ======================= LayerNorm (fp32 in -> fp16 out) =====================
__global__ void ln_kernel(const float* __restrict__ x,
                          const float* __restrict__ g,
                          const float* __restrict__ b,
                          __half* __restrict__ out) {
    int row = blockIdx.x;
    const float* xr = x + (size_t)row * EMB;
    float v[4];
    float s = 0.f, ss = 0.f;
#pragma unroll
    for (int i = 0; i < 4; i++) {
        v[i] = xr[threadIdx.x + i * 256];
        s += v[i]; ss += v[i] * v[i];
    }
#pragma unroll
    for (int m = 16; m; m >>= 1) {
        s  += __shfl_xor_sync(0xffffffffu, s,  m);
        ss += __shfl_xor_sync(0xffffffffu, ss, m);
    }
    __shared__ float red[2][8];
    int warp = threadIdx.x >> 5, lane = threadIdx.x & 31;
    if (lane == 0) { red[0][warp] = s; red[1][warp] = ss; }
    __syncthreads();
    float S = 0.f, SS = 0.f;
#pragma unroll
    for (int w = 0; w < 8; w++) { S += red[0][w]; SS += red[1][w]; }
    float mean = S * (1.f / EMB);
    float var  = SS * (1.f / EMB) - mean * mean;
    float inv  = rsqrtf(var + 1e-5f);
    __half* orow = out + (size_t)row * EMB;
#pragma unroll
    for (int i = 0; i < 4; i++) {
        int e = threadIdx.x + i * 256;
        orow[e] = __float2half((v[i] - mean) * inv * g[e] + b[e]);
    }
}

// ======================= Flash attention, fp16 tensor cores ==================
// Br=128 (8 warps x 16 rows), Bc=64, d=64; all operands fp16; P in registers.
#define FQSLAB 520
#define FKSLAB 264
#define FQSUB  2080
#define FKSUB  1056

__global__ void __launch_bounds__(256)
flash_mma(const __half* __restrict__ Q, const __half* __restrict__ Kg,
          const __half* __restrict__ Vt, __half* __restrict__ O) {
    __shared__ uint32_t Qs[2 * FQSUB];
    __shared__ uint32_t Ks[2 * FKSUB];
    __shared__ uint32_t Vs[2 * FKSUB];
    int t = threadIdx.x, lane = t & 31, w = t >> 5;
    int g = lane >> 2, tg = lane & 3;
    int bh = blockIdx.y;
    int row0 = blockIdx.x * 128;
    size_t baseQ = (size_t)(bh >> 4) * SEQ * EMB + (size_t)(bh & 15) * DHEAD;
    size_t baseV = (size_t)bh * DHEAD * SEQ;
    const __half2 qscale = __float2half2_rn(0.125f);

    for (int i = t; i < 1024; i += 256) {
        int r = i >> 3, q = i & 7;
        uint4 p = *(const uint4*)(Q + baseQ + (size_t)(row0 + r) * EMB + q * 8);
        uint32_t un[4] = {p.x, p.y, p.z, p.w};
#pragma unroll
        for (int jj = 0; jj < 4; jj++) {
            __half2 hv = *reinterpret_cast<__half2*>(&un[jj]);
            hv = __hmul2(hv, qscale);
            int u = q * 4 + jj;
            int s_ = u >> 4, uu = u & 15;
            Qs[s_ * FQSUB + (uu & 3) * FQSLAB + r * 4 + (uu >> 2)]
                = *reinterpret_cast<uint32_t*>(&hv);
        }
    }
    __syncthreads();

    int rA = w * 16 + g, rB = rA + 8;
    uint4 qfA[2], qfB[2];
#pragma unroll
    for (int sub = 0; sub < 2; sub++) {
        qfA[sub] = *(const uint4*)&Qs[sub * FQSUB + tg * FQSLAB + rA * 4];
        qfB[sub] = *(const uint4*)&Qs[sub * FQSUB + tg * FQSLAB + rB * 4];
    }

    float m0 = -1e30f, m1 = -1e30f, l0 = 0.f, l1 = 0.f;
    float oacc[8][4];
#pragma unroll
    for (int i = 0; i < 8; i++)
#pragma unroll
        for (int j = 0; j < 4; j++) oacc[i][j] = 0.f;

    for (int kt = 0; kt < SEQ; kt += 64) {
        __syncthreads();
#pragma unroll
        for (int ii = 0; ii < 2; ii++) {
            int i = t + ii * 256;
            int r = i >> 3, q = i & 7;
            uint4 pk = *(const uint4*)(Kg + baseQ + (size_t)(kt + r) * EMB + q * 8);
            uint4 pv = *(const uint4*)(Vt + baseV + (size_t)r * SEQ + kt + q * 8);
            uint32_t ku[4] = {pk.x, pk.y, pk.z, pk.w};
            uint32_t vu[4] = {pv.x, pv.y, pv.z, pv.w};
#pragma unroll
            for (int jj = 0; jj < 4; jj++) {
                int u = q * 4 + jj;
                int s_ = u >> 4, uu = u & 15;
                int off = s_ * FKSUB + (uu & 3) * FKSLAB + r * 4 + (uu >> 2);
                Ks[off] = ku[jj];
                Vs[off] = vu[jj];
            }
        }
        __syncthreads();

        float sacc[8][4];
#pragma unroll
        for (int i = 0; i < 8; i++)
#pragma unroll
            for (int j = 0; j < 4; j++) sacc[i][j] = 0.f;
#pragma unroll
        for (int sub = 0; sub < 2; sub++) {
            uint4 qa = qfA[sub], qb = qfB[sub];
#pragma unroll
            for (int nb = 0; nb < 8; nb++) {
                uint4 kf = *(const uint4*)&Ks[sub * FKSUB + tg * FKSLAB
                                              + (nb * 8 + g) * 4];
                mmaf16(sacc[nb], qa.x, qb.x, qa.y, qb.y, kf.x, kf.y);
                mmaf16(sacc[nb], qa.z, qb.z, qa.w, qb.w, kf.z, kf.w);
            }
        }

        float mxA = -1e30f, mxB = -1e30f;
#pragma unroll
        for (int nb = 0; nb < 8; nb++) {
            mxA = fmaxf(mxA, fmaxf(sacc[nb][0], sacc[nb][1]));
            mxB = fmaxf(mxB, fmaxf(sacc[nb][2], sacc[nb][3]));
        }
        mxA = fmaxf(mxA, __shfl_xor_sync(0xffffffffu, mxA, 1));
        mxA = fmaxf(mxA, __shfl_xor_sync(0xffffffffu, mxA, 2));
        mxB = fmaxf(mxB, __shfl_xor_sync(0xffffffffu, mxB, 1));
        mxB = fmaxf(mxB, __shfl_xor_sync(0xffffffffu, mxB, 2));
        float mnA = fmaxf(m0, mxA), mnB = fmaxf(m1, mxB);
        float cA = __expf(m0 - mnA), cB = __expf(m1 - mnB);
        m0 = mnA; m1 = mnB;
        float rsA = 0.f, rsB = 0.f;
#pragma unroll
        for (int nb = 0; nb < 8; nb++) {
            sacc[nb][0] = __expf(sacc[nb][0] - mnA);
            sacc[nb][1] = __expf(sacc[nb][1] - mnA);
            sacc[nb][2] = __expf(sacc[nb][2] - mnB);
            sacc[nb][3] = __expf(sacc[nb][3] - mnB);
            rsA += sacc[nb][0] + sacc[nb][1];
            rsB += sacc[nb][2] + sacc[nb][3];
        }
        rsA += __shfl_xor_sync(0xffffffffu, rsA, 1);
        rsA += __shfl_xor_sync(0xffffffffu, rsA, 2);
        rsB += __shfl_xor_sync(0xffffffffu, rsB, 1);
        rsB += __shfl_xor_sync(0xffffffffu, rsB, 2);
        l0 = l0 * cA + rsA;
        l1 = l1 * cB + rsB;
#pragma unroll
        for (int db = 0; db < 8; db++) {
            oacc[db][0] *= cA; oacc[db][1] *= cA;
            oacc[db][2] *= cB; oacc[db][3] *= cB;
        }

        uint32_t a0[4], a1[4], a2[4], a3[4];
#pragma unroll
        for (int s = 0; s < 4; s++) {
            a0[s] = packh2(sacc[2 * s][0],     sacc[2 * s][1]);
            a1[s] = packh2(sacc[2 * s][2],     sacc[2 * s][3]);
            a2[s] = packh2(sacc[2 * s + 1][0], sacc[2 * s + 1][1]);
            a3[s] = packh2(sacc[2 * s + 1][2], sacc[2 * s + 1][3]);
        }

#pragma unroll
        for (int db = 0; db < 8; db++)
#pragma unroll
            for (int sub = 0; sub < 2; sub++) {
                uint4 vf = *(const uint4*)&Vs[sub * FKSUB + tg * FKSLAB
                                              + (db * 8 + g) * 4];
                int s0 = 2 * sub, s1 = s0 + 1;
                mmaf16(oacc[db], a0[s0], a1[s0], a2[s0], a3[s0], vf.x, vf.y);
                mmaf16(oacc[db], a0[s1], a1[s1], a2[s1], a3[s1], vf.z, vf.w);
            }
    }

    float iA = 1.f / l0, iB = 1.f / l1;
#pragma unroll
    for (int db = 0; db < 8; db++) {
        int c = db * 8 + 2 * tg;
        *(uint32_t*)(O + baseQ + (size_t)(row0 + rA) * EMB + c) =
            packh2(oacc[db][0] * iA, oacc[db][1] * iA);
        *(uint32_t*)(O + baseQ + (size_t)(row0 + rB) * EMB + c) =
            packh2(oacc[db][2] * iB, oacc[db][3] * iB);
    }
}

// ======================= host orchestration =================================
extern "C" void kernel_launch(void* const* d_in, const int* in_sizes, int n_in,
                              void* d_out, int out_size) {
    const float* x     = (const float*)d_in[0];
    const float* Wq    = (const float*)d_in[1];
    const float* Wk    = (const float*)d_in[2];
    const float* Wv    = (const float*)d_in[3];
    const float* Wproj = (const float*)d_in[4];
    const float* bproj = (const float*)d_in[5];
    const float* W1    = (const float*)d_in[6];
    const float* b1    = (const float*)d_in[7];
    const float* W2    = (const float*)d_in[8];
    const float* b2    = (const float*)d_in[9];
    const float* g1    = (const float*)d_in[10];
    const float* be1   = (const float*)d_in[11];
    const float* g2    = (const float*)d_in[12];
    const float* be2   = (const float*)d_in[13];
    float* out = (float*)d_out;

    void *ph, *pq, *pk, *pv, *pvt, *pattn, *px1, *pffn;
    void *pwq, *pwk, *pwv, *pwp, *pw1, *pw2;
    cudaGetSymbolAddress(&ph,    g_h);
    cudaGetSymbolAddress(&pq,    g_q);
    cudaGetSymbolAddress(&pk,    g_k);
    cudaGetSymbolAddress(&pv,    g_v);
    cudaGetSymbolAddress(&pvt,   g_vt);
    cudaGetSymbolAddress(&pattn, g_attn);
    cudaGetSymbolAddress(&px1,   g_x1);
    cudaGetSymbolAddress(&pffn,  g_ffn);
    cudaGetSymbolAddress(&pwq,   g_wqt);
    cudaGetSymbolAddress(&pwk,   g_wkt);
    cudaGetSymbolAddress(&pwv,   g_wvt);
    cudaGetSymbolAddress(&pwp,   g_wpt);
    cudaGetSymbolAddress(&pw1,   g_w1t);
    cudaGetSymbolAddress(&pw2,   g_w2t);
    __half* f_h    = (__half*)ph;
    __half* f_q    = (__half*)pq;
    __half* f_k    = (__half*)pk;
    __half* f_v    = (__half*)pv;
    __half* f_vt   = (__half*)pvt;
    __half* f_attn = (__half*)pattn;
    float*  f_x1   = (float*)px1;
    __half* f_ffn  = (__half*)pffn;

    cudaFuncSetAttribute(gemm_mma, cudaFuncAttributeMaxDynamicSharedMemorySize,
                         G_SMEM);

    dim3 tb(32, 8);
    dim3 gP(EMB / 128, ROWS / 128);     // (8, 32)
    dim3 gF1(FFDIM / 128, ROWS / 128);  // (32, 32)

    ln_kernel<<<ROWS, 256>>>(x, g1, be1, f_h);
    transpose_w<<<dim3(EMB / 32, EMB / 32), tb>>>(Wq, (__half*)pwq, EMB, EMB, 1);
    transpose_w<<<dim3(EMB / 32, EMB / 32), tb>>>(Wk, (__half*)pwk, EMB, EMB, 1);
    transpose_w<<<dim3(EMB / 32, EMB / 32), tb>>>(Wv, (__half*)pwv, EMB, EMB, 1);
    transpose_w<<<dim3(EMB / 32, EMB / 32), tb>>>(Wproj, (__half*)pwp, EMB, EMB, 0);

    gemm_mma<<<gP, 256, G_SMEM>>>(f_h, (__half*)pwq, f_q, nullptr, nullptr, 0, EMB, EMB, 1);
    gemm_mma<<<gP, 256, G_SMEM>>>(f_h, (__half*)pwk, f_k, nullptr, nullptr, 0, EMB, EMB, 1);
    gemm_mma<<<gP, 256, G_SMEM>>>(f_h, (__half*)pwv, f_v, nullptr, nullptr, 0, EMB, EMB, 1);

    transpose_v<<<dim3(SEQ / 32, DHEAD / 32, 32), tb>>>(
        (const unsigned short*)pv, (unsigned short*)pvt);
    flash_mma<<<dim3(SEQ / 128, 32), 256>>>(f_q, f_k, f_vt, f_attn);

    gemm_mma<<<gP, 256, G_SMEM>>>(f_attn, (__half*)pwp, f_x1, bproj, x, 0, EMB, EMB, 0);
    ln_kernel<<<ROWS, 256>>>(f_x1, g2, be2, f_h);

    transpose_w<<<dim3(FFDIM / 32, EMB / 32), tb>>>(W1, (__half*)pw1, EMB, FFDIM, 0);
    transpose_w<<<dim3(EMB / 32, FFDIM / 32), tb>>>(W2, (__half*)pw2, FFDIM, EMB, 0);

    gemm_mma<<<gF1, 256, G_SMEM>>>(f_h, (__half*)pw1, f_ffn, b1, nullptr, 1, EMB, FFDIM, 1);
    gemm_mma<<<gP, 256, G_SMEM>>>(f_ffn, (__half*)pw2, out, b2, f_x1, 0, FFDIM, EMB, 0);
}